// round 12
// baseline (speedup 1.0000x reference)
#include <cuda_runtime.h>
#include <cuda_bf16.h>
#include <math.h>
#include <stdint.h>

#define D_MODEL 1024
#define N_HEADS 16
#define HEAD_DIM 64
#define BATCH 2
#define SEQ 2048
#define M_TOT (BATCH * SEQ)   /* 4096 */

/* ---- scratch (allocation-free: __device__ globals) ---- */
__device__ float g_q[(size_t)M_TOT * D_MODEL];   /* q, later reused as O */
__device__ float g_k[(size_t)M_TOT * D_MODEL];
__device__ float g_v[(size_t)M_TOT * D_MODEL];
__device__ float g_xr[(size_t)M_TOT * D_MODEL];          /* tf32-rounded x */
__device__ float g_wr[4][(size_t)D_MODEL * D_MODEL];     /* tf32-rounded W */
__device__ __nv_bfloat16 g_qh[(size_t)M_TOT * D_MODEL];
__device__ __nv_bfloat16 g_ql[(size_t)M_TOT * D_MODEL];
__device__ __nv_bfloat16 g_kh[(size_t)M_TOT * D_MODEL];
__device__ __nv_bfloat16 g_kl[(size_t)M_TOT * D_MODEL];
__device__ __nv_bfloat16 g_vth[(size_t)M_TOT * D_MODEL]; /* [bh][d][S] */
__device__ __nv_bfloat16 g_vtl[(size_t)M_TOT * D_MODEL];

__device__ __forceinline__ uint32_t smem_to_u32(const void* p) {
    uint32_t a;
    asm("{ .reg .u64 t; cvta.to.shared.u64 t, %1; cvt.u32.u64 %0, t; }" : "=r"(a) : "l"(p));
    return a;
}

#define LDSM_X4(r0, r1, r2, r3, addr) \
    asm volatile("ldmatrix.sync.aligned.m8n8.x4.shared.b16 {%0,%1,%2,%3}, [%4];" \
                 : "=r"(r0), "=r"(r1), "=r"(r2), "=r"(r3) : "r"(addr))

#define MMA_BF16(c, a, b) \
    asm volatile("mma.sync.aligned.m16n8k16.row.col.f32.bf16.bf16.f32 " \
                 "{%0,%1,%2,%3},{%4,%5,%6,%7},{%8,%9},{%0,%1,%2,%3};" \
                 : "+f"((c)[0]), "+f"((c)[1]), "+f"((c)[2]), "+f"((c)[3]) \
                 : "r"((a)[0]), "r"((a)[1]), "r"((a)[2]), "r"((a)[3]), \
                   "r"((b)[0]), "r"((b)[1]))

#define MMA_TF32(c, a, b) \
    asm volatile("mma.sync.aligned.m16n8k8.row.col.f32.tf32.tf32.f32 " \
                 "{%0,%1,%2,%3},{%4,%5,%6,%7},{%8,%9},{%0,%1,%2,%3};" \
                 : "+f"((c)[0]), "+f"((c)[1]), "+f"((c)[2]), "+f"((c)[3]) \
                 : "r"((a)[0]), "r"((a)[1]), "r"((a)[2]), "r"((a)[3]), \
                   "r"((b)[0]), "r"((b)[1]))

#define CP_ASYNC16(saddr, gptr) \
    asm volatile("cp.async.cg.shared.global [%0], [%1], 16;" \
                 :: "r"(saddr), "l"(gptr) : "memory")
#define CP_COMMIT() asm volatile("cp.async.commit_group;" ::: "memory")
#define CP_WAIT0()  asm volatile("cp.async.wait_group 0;" ::: "memory")
#define CP_WAIT1()  asm volatile("cp.async.wait_group 1;" ::: "memory")

__device__ __forceinline__ uint32_t pk_bf16x2(__nv_bfloat16 a, __nv_bfloat16 b) {
    return (uint32_t)__bfloat16_as_ushort(a) | ((uint32_t)__bfloat16_as_ushort(b) << 16);
}
__device__ __forceinline__ float tf32r(float x) {
    uint32_t r;
    asm("cvt.rna.tf32.f32 %0, %1;" : "=r"(r) : "f"(x));
    return __uint_as_float(r);
}

/* ============================================================
 * Merged fp32 -> tf32 rounding for x + all 4 weights (1 launch).
 * ============================================================ */
__global__ void __launch_bounds__(256)
round_all_kernel(const float* __restrict__ x,
                 const float* __restrict__ w0, const float* __restrict__ w1,
                 const float* __restrict__ w2, const float* __restrict__ w3,
                 float* __restrict__ xr, float* __restrict__ wr)
{
    const int b = blockIdx.x;
    const float* src;
    float* dst;
    int lb;
    if (b < 4096) { src = x; dst = xr; lb = b; }
    else {
        const int r = b - 4096;
        const int w = r >> 10;
        src = (w == 0) ? w0 : (w == 1) ? w1 : (w == 2) ? w2 : w3;
        dst = wr + (size_t)w * D_MODEL * D_MODEL;
        lb = r & 1023;
    }
    const size_t i = ((size_t)lb * 256 + threadIdx.x) * 4;
    float4 v = *(const float4*)(src + i);
    v.x = tf32r(v.x); v.y = tf32r(v.y); v.z = tf32r(v.z); v.w = tf32r(v.w);
    *(float4*)(dst + i) = v;
}

/* ============================================================
 * tf32 single-pass GEMM, 512 threads (16 warps, 4x4), warp tile
 * 32x32, 3-stage cp.async pipeline, ONE syncthreads per chunk.
 * Fragments via ldmatrix.b16 (byte-exact for tf32).
 * ============================================================ */
#define TPAD 144
#define TTILE (128 * TPAD)    /* 18432 */
#define TSTG (2 * TTILE)      /* 36864 per stage (A + B) */
#define GEMM_SMEM (3 * TSTG)  /* 110592 */

__global__ void __launch_bounds__(512, 2)
gemm_tf32_kernel(const float* __restrict__ A, const float* __restrict__ B,
                 float* __restrict__ C, int M, int N, int K)
{
    extern __shared__ __align__(16) char smem[];
    const uint32_t su = smem_to_u32(smem);

    const int tid    = threadIdx.x;
    const int lane   = tid & 31;
    const int wid    = tid >> 5;        /* 0..15 */
    const int warp_m = wid >> 2;        /* 0..3 */
    const int warp_n = wid & 3;         /* 0..3 */
    const int m0 = blockIdx.y * 128;
    const int n0 = blockIdx.x * 128;

    const int nchunks = K / 32;         /* 32 */

    /* stage fill: 2048 x 16B transfers, 4 per thread */
    auto issue_stage = [&](int s, int i) {
        const uint32_t sb = su + s * TSTG;
        #pragma unroll
        for (int t = 0; t < 2; t++) {
            const int idx = tid + t * 512;          /* 0..1023 */
            const int row = idx >> 3, c = idx & 7;
            const uint32_t so = (uint32_t)row * TPAD + c * 16;
            const size_t ga = (size_t)(m0 + row) * K + i * 32 + c * 4;
            const size_t gb = (size_t)(n0 + row) * K + i * 32 + c * 4;
            CP_ASYNC16(sb + so, A + ga);
            CP_ASYNC16(sb + TTILE + so, B + gb);
        }
        CP_COMMIT();
    };

    issue_stage(0, 0);
    issue_stage(1, 1);

    /* ldmatrix bases: warp tile rows (16-row windows, two 16B halves) */
    const uint32_t a_ld = su + (uint32_t)(warp_m * 32 + (lane & 15)) * TPAD + (lane >> 4) * 16;
    const uint32_t b_ld = su + TTILE + (uint32_t)(warp_n * 32 + (lane & 15)) * TPAD + (lane >> 4) * 16;

    float acc[2][4][4] = {};

    for (int i = 0; i < nchunks; i++) {
        if (i == nchunks - 1) { CP_WAIT0(); }
        else                  { CP_WAIT1(); }
        __syncthreads();

        /* prefetch 2 stages ahead: target buffer was consumed at iter i-1,
           which every warp finished before the barrier above */
        if (i + 2 < nchunks) issue_stage((i + 2) % 3, i + 2);

        const uint32_t stb = (uint32_t)(i % 3) * TSTG;

        #pragma unroll
        for (int ks = 0; ks < 4; ks++) {
            uint32_t af[2][4];
            #pragma unroll
            for (int mt = 0; mt < 2; mt++)
                LDSM_X4(af[mt][0], af[mt][1], af[mt][2], af[mt][3],
                        a_ld + stb + mt * 16 * TPAD + ks * 32);
            uint32_t bf[4][2];
            #pragma unroll
            for (int nb = 0; nb < 2; nb++) {
                uint32_t r0, r1, r2, r3;
                LDSM_X4(r0, r1, r2, r3, b_ld + stb + nb * 16 * TPAD + ks * 32);
                bf[nb * 2][0]     = r0; bf[nb * 2][1]     = r2;
                bf[nb * 2 + 1][0] = r1; bf[nb * 2 + 1][1] = r3;
            }
            #pragma unroll
            for (int mt = 0; mt < 2; mt++)
                #pragma unroll
                for (int nt = 0; nt < 4; nt++)
                    MMA_TF32(acc[mt][nt], af[mt], bf[nt]);
        }
    }

    #pragma unroll
    for (int mt = 0; mt < 2; mt++) {
        const int m = m0 + warp_m * 32 + mt * 16 + (lane >> 2);
        #pragma unroll
        for (int nt = 0; nt < 4; nt++) {
            const int n = n0 + warp_n * 32 + nt * 8 + (lane & 3) * 2;
            *(float2*)(C + (size_t)m * N + n) =
                make_float2(acc[mt][nt][0], acc[mt][nt][1]);
            *(float2*)(C + (size_t)(m + 8) * N + n) =
                make_float2(acc[mt][nt][2], acc[mt][nt][3]);
        }
    }
}

/* ============================================================
 * Fused RoPE for Q and K -> bf16 hi/lo (unchanged).
 * ============================================================ */
__global__ void __launch_bounds__(256)
rope2_kernel(const float* __restrict__ q, const float* __restrict__ k,
             __nv_bfloat16* __restrict__ qh, __nv_bfloat16* __restrict__ ql,
             __nv_bfloat16* __restrict__ kh, __nv_bfloat16* __restrict__ kl)
{
    __shared__ float invf[32];
    const int tid = threadIdx.x;
    if (tid < 32) invf[tid] = (float)pow(10000.0, -(double)tid / 32.0);
    __syncthreads();

    const int bs   = blockIdx.x * 8 + (tid >> 5);
    const int lane = tid & 31;
    const int pos  = bs & (SEQ - 1);

    float s1, c1, s2, c2;
    sincosf((float)pos * invf[(2 * lane) & 31],     &s1, &c1);
    sincosf((float)pos * invf[(2 * lane + 1) & 31], &s2, &c2);

    const size_t base = (size_t)bs * D_MODEL;
    #pragma unroll
    for (int h = 0; h < N_HEADS; h++) {
        const size_t ro = base + h * 64;
        {
            float x0 = q[ro + 2 * lane], x1 = q[ro + 2 * lane + 1];
            float y0 = (x0 * c1 - x1 * s1) * 0.125f;
            float y1 = (x0 * s2 + x1 * c2) * 0.125f;
            __nv_bfloat16 h0 = __float2bfloat16_rn(y0);
            __nv_bfloat16 h1 = __float2bfloat16_rn(y1);
            qh[ro + lane]      = h0;
            ql[ro + lane]      = __float2bfloat16_rn(y0 - __bfloat162float(h0));
            qh[ro + 32 + lane] = h1;
            ql[ro + 32 + lane] = __float2bfloat16_rn(y1 - __bfloat162float(h1));
        }
        {
            float x0 = k[ro + 2 * lane], x1 = k[ro + 2 * lane + 1];
            float y0 = x0 * c1 - x1 * s1;
            float y1 = x0 * s2 + x1 * c2;
            __nv_bfloat16 h0 = __float2bfloat16_rn(y0);
            __nv_bfloat16 h1 = __float2bfloat16_rn(y1);
            kh[ro + lane]      = h0;
            kl[ro + lane]      = __float2bfloat16_rn(y0 - __bfloat162float(h0));
            kh[ro + 32 + lane] = h1;
            kl[ro + 32 + lane] = __float2bfloat16_rn(y1 - __bfloat162float(h1));
        }
    }
}

/* ============================================================
 * V transpose + split (unchanged).
 * ============================================================ */
__global__ void __launch_bounds__(256)
vtrans_kernel(const float* __restrict__ v,
              __nv_bfloat16* __restrict__ vth, __nv_bfloat16* __restrict__ vtl)
{
    __shared__ float t[64][65];
    const int sblk = blockIdx.x;
    const int bh   = blockIdx.y;
    const int tid  = threadIdx.x;

    {
        const int row = tid >> 2;
        const int c0  = (tid & 3) * 16;
        const size_t gaddr = ((size_t)(bh >> 4) * SEQ + sblk * 64 + row) * D_MODEL
                           + (bh & 15) * 64 + c0;
        #pragma unroll
        for (int f = 0; f < 4; f++) {
            float4 vv = *(const float4*)(v + gaddr + f * 4);
            t[row][c0 + f * 4 + 0] = vv.x; t[row][c0 + f * 4 + 1] = vv.y;
            t[row][c0 + f * 4 + 2] = vv.z; t[row][c0 + f * 4 + 3] = vv.w;
        }
    }
    __syncthreads();

    const int d  = tid >> 2;
    const int k0 = (tid & 3) * 16;
    __nv_bfloat16 hv[16], lv[16];
    #pragma unroll
    for (int kk = 0; kk < 16; kk++) {
        float x = t[k0 + kk][d];
        hv[kk] = __float2bfloat16_rn(x);
        lv[kk] = __float2bfloat16_rn(x - __bfloat162float(hv[kk]));
    }
    const size_t dst = ((size_t)bh * 64 + d) * SEQ + sblk * 64 + k0;
    *(uint4*)(vth + dst)     = *(uint4*)(hv);
    *(uint4*)(vth + dst + 8) = *(uint4*)(hv + 8);
    *(uint4*)(vtl + dst)     = *(uint4*)(lv);
    *(uint4*)(vtl + dst + 8) = *(uint4*)(lv + 8);
}

/* ============================================================
 * Flash attention, causal, split-bf16 mma.sync, cp.async pipeline,
 * qb-paired load balancing (unchanged).
 * ============================================================ */
#define AQP 144
#define AQTILE (128 * AQP)
#define AKTILE (64 * AQP)
#define ASTAGE (4 * AKTILE)
#define ATTN_SMEM (2 * AQTILE + 2 * ASTAGE)  /* 110592 */
#define NQB (SEQ / 128)                      /* 16 */

__global__ void __launch_bounds__(256, 2)
attn_mma_kernel(const __nv_bfloat16* __restrict__ qh, const __nv_bfloat16* __restrict__ ql,
                const __nv_bfloat16* __restrict__ kh, const __nv_bfloat16* __restrict__ kl,
                const __nv_bfloat16* __restrict__ vth, const __nv_bfloat16* __restrict__ vtl,
                float* __restrict__ o)
{
    extern __shared__ __align__(16) char sm[];
    const uint32_t su = smem_to_u32(sm);

    const int bh   = blockIdx.y;
    const int tid  = threadIdx.x;
    const int lane = tid & 31;
    const int wid  = tid >> 5;

    const int b = bh >> 4, h = bh & 15;
    const size_t qkrow0 = ((size_t)b * SEQ) * D_MODEL + (size_t)h * 64;
    const size_t vtrow0 = ((size_t)bh * 64) * SEQ;

    const uint32_t a_ld = su + (uint32_t)(wid * 16 + (lane & 15)) * AQP + (lane >> 4) * 16;
    const uint32_t t_ld = su + 2 * AQTILE + (uint32_t)(lane & 15) * AQP + (lane >> 4) * 16;

    auto issue_stage = [&](int s, int kb) {
        const uint32_t sb = su + 2 * AQTILE + s * ASTAGE;
        #pragma unroll
        for (int i = 0; i < 2; i++) {
            const int idx = tid + i * 256;
            const int row = idx >> 3, c = idx & 7;
            const uint32_t so = (uint32_t)row * AQP + c * 16;
            const size_t gk = qkrow0 + (size_t)(kb * 64 + row) * D_MODEL + c * 8;
            const size_t gv = vtrow0 + (size_t)row * SEQ + kb * 64 + c * 8;
            CP_ASYNC16(sb + 0 * AKTILE + so, kh + gk);
            CP_ASYNC16(sb + 1 * AKTILE + so, kl + gk);
            CP_ASYNC16(sb + 2 * AKTILE + so, vth + gv);
            CP_ASYNC16(sb + 3 * AKTILE + so, vtl + gv);
        }
        CP_COMMIT();
    };

    #pragma unroll 1
    for (int qi = 0; qi < 2; qi++) {
        const int qb = (qi == 0) ? blockIdx.x : (NQB - 1 - blockIdx.x);

        {
            const int lrow = tid >> 1, lhalf = tid & 1;
            const uint32_t sts = (uint32_t)lrow * AQP + lhalf * 64;
            const size_t g = qkrow0 + (size_t)(qb * 128 + lrow) * D_MODEL + lhalf * 32;
            const uint4* sh = (const uint4*)(qh + g);
            const uint4* sl = (const uint4*)(ql + g);
            uint4* dh = (uint4*)(sm + sts);
            uint4* dl = (uint4*)(sm + AQTILE + sts);
            #pragma unroll
            for (int f = 0; f < 4; f++) { dh[f] = sh[f]; dl[f] = sl[f]; }
        }

        const int nkb = 2 * qb + 2;
        issue_stage(0, 0);

        float acc[8][4] = {};
        float mo1 = -1e30f, mo2 = -1e30f, l1 = 0.0f, l2 = 0.0f;
        const int q1g = qb * 128 + wid * 16 + (lane >> 2);
        const int warp_qmax = qb * 128 + wid * 16 + 15;

        for (int kb = 0; kb < nkb; kb++) {
            const int s = kb & 1;
            if (kb + 1 < nkb) { issue_stage(s ^ 1, kb + 1); CP_WAIT1(); }
            else              { CP_WAIT0(); }
            __syncthreads();

            const bool tile_active = (kb * 64 <= warp_qmax);

            if (tile_active) {
                const uint32_t kb_ld = t_ld + s * ASTAGE;

                float sc[8][4] = {};
                #pragma unroll
                for (int ks = 0; ks < 4; ks++) {
                    uint32_t ah[4], al[4];
                    LDSM_X4(ah[0], ah[1], ah[2], ah[3], a_ld + ks * 32 + 0 * AQTILE);
                    LDSM_X4(al[0], al[1], al[2], al[3], a_ld + ks * 32 + 1 * AQTILE);
                    #pragma unroll
                    for (int nb = 0; nb < 4; nb++) {
                        if (kb * 64 + nb * 16 > warp_qmax) continue;
                        uint32_t r0, r1, r2, r3, q0, q1, q2, q3;
                        LDSM_X4(r0, r1, r2, r3, kb_ld + nb * 16 * AQP + ks * 32 + 0 * AKTILE);
                        LDSM_X4(q0, q1, q2, q3, kb_ld + nb * 16 * AQP + ks * 32 + 1 * AKTILE);
                        uint32_t be[2] = {r0, r2}, bo[2] = {r1, r3};
                        uint32_t le[2] = {q0, q2}, lo_[2] = {q1, q3};
                        MMA_BF16(sc[2 * nb],     ah, be); MMA_BF16(sc[2 * nb],     ah, le); MMA_BF16(sc[2 * nb],     al, be);
                        MMA_BF16(sc[2 * nb + 1], ah, bo); MMA_BF16(sc[2 * nb + 1], ah, lo_); MMA_BF16(sc[2 * nb + 1], al, bo);
                    }
                }

                if (kb * 64 + 63 > qb * 128 + wid * 16) {
                    #pragma unroll
                    for (int j = 0; j < 8; j++) {
                        const int c = kb * 64 + j * 8 + (lane & 3) * 2;
                        if (c     > q1g)     sc[j][0] = -1e30f;
                        if (c + 1 > q1g)     sc[j][1] = -1e30f;
                        if (c     > q1g + 8) sc[j][2] = -1e30f;
                        if (c + 1 > q1g + 8) sc[j][3] = -1e30f;
                    }
                }

                float m1 = -1e30f, m2 = -1e30f;
                #pragma unroll
                for (int j = 0; j < 8; j++) {
                    m1 = fmaxf(m1, fmaxf(sc[j][0], sc[j][1]));
                    m2 = fmaxf(m2, fmaxf(sc[j][2], sc[j][3]));
                }
                m1 = fmaxf(m1, __shfl_xor_sync(0xffffffffu, m1, 1));
                m1 = fmaxf(m1, __shfl_xor_sync(0xffffffffu, m1, 2));
                m2 = fmaxf(m2, __shfl_xor_sync(0xffffffffu, m2, 1));
                m2 = fmaxf(m2, __shfl_xor_sync(0xffffffffu, m2, 2));
                const float mn1 = fmaxf(mo1, m1), mn2 = fmaxf(mo2, m2);
                const float sc1 = __expf(mo1 - mn1), sc2 = __expf(mo2 - mn2);
                float sum1 = 0.0f, sum2 = 0.0f;
                #pragma unroll
                for (int j = 0; j < 8; j++) {
                    sc[j][0] = __expf(sc[j][0] - mn1); sum1 += sc[j][0];
                    sc[j][1] = __expf(sc[j][1] - mn1); sum1 += sc[j][1];
                    sc[j][2] = __expf(sc[j][2] - mn2); sum2 += sc[j][2];
                    sc[j][3] = __expf(sc[j][3] - mn2); sum2 += sc[j][3];
                }
                sum1 += __shfl_xor_sync(0xffffffffu, sum1, 1);
                sum1 += __shfl_xor_sync(0xffffffffu, sum1, 2);
                sum2 += __shfl_xor_sync(0xffffffffu, sum2, 1);
                sum2 += __shfl_xor_sync(0xffffffffu, sum2, 2);
                l1 = l1 * sc1 + sum1; l2 = l2 * sc2 + sum2;
                mo1 = mn1; mo2 = mn2;
                #pragma unroll
                for (int j = 0; j < 8; j++) {
                    acc[j][0] *= sc1; acc[j][1] *= sc1;
                    acc[j][2] *= sc2; acc[j][3] *= sc2;
                }

                #pragma unroll
                for (int ks = 0; ks < 4; ks++) {
                    if (kb * 64 + ks * 16 > warp_qmax) continue;
                    uint32_t ph[4], pl[4];
                    #pragma unroll
                    for (int t2 = 0; t2 < 2; t2++) {
                        const int j = 2 * ks + t2;
                        __nv_bfloat16 h0 = __float2bfloat16_rn(sc[j][0]);
                        __nv_bfloat16 h1 = __float2bfloat16_rn(sc[j][1]);
                        __nv_bfloat16 h2 = __float2bfloat16_rn(sc[j][2]);
                        __nv_bfloat16 h3 = __float2bfloat16_rn(sc[j][3]);
                        ph[2 * t2]     = pk_bf16x2(h0, h1);
                        ph[2 * t2 + 1] = pk_bf16x2(h2, h3);
                        pl[2 * t2]     = pk_bf16x2(
                            __float2bfloat16_rn(sc[j][0] - __bfloat162float(h0)),
                            __float2bfloat16_rn(sc[j][1] - __bfloat162float(h1)));
                        pl[2 * t2 + 1] = pk_bf16x2(
                            __float2bfloat16_rn(sc[j][2] - __bfloat162float(h2)),
                            __float2bfloat16_rn(sc[j][3] - __bfloat162float(h3)));
                    }
                    #pragma unroll
                    for (int nb = 0; nb < 4; nb++) {
                        uint32_t r0, r1, r2, r3, q0, q1, q2, q3;
                        LDSM_X4(r0, r1, r2, r3, kb_ld + nb * 16 * AQP + ks * 32 + 2 * AKTILE);
                        LDSM_X4(q0, q1, q2, q3, kb_ld + nb * 16 * AQP + ks * 32 + 3 * AKTILE);
                        uint32_t be[2] = {r0, r2}, bo[2] = {r1, r3};
                        uint32_t le[2] = {q0, q2}, lo_[2] = {q1, q3};
                        MMA_BF16(acc[2 * nb],     ph, be); MMA_BF16(acc[2 * nb],     ph, le); MMA_BF16(acc[2 * nb],     pl, be);
                        MMA_BF16(acc[2 * nb + 1], ph, bo); MMA_BF16(acc[2 * nb + 1], ph, lo_); MMA_BF16(acc[2 * nb + 1], pl, bo);
                    }
                }
            }
            __syncthreads();
        }

        const float i1 = 1.0f / l1, i2 = 1.0f / l2;
        const size_t r1a = qkrow0 + (size_t)(qb * 128 + wid * 16 + (lane >> 2)) * D_MODEL;
        const size_t r2a = r1a + 8 * D_MODEL;
        #pragma unroll
        for (int j = 0; j < 8; j++) {
            const int c = j * 8 + (lane & 3) * 2;
            *(float2*)(o + r1a + c) = make_float2(tf32r(acc[j][0] * i1), tf32r(acc[j][1] * i1));
            *(float2*)(o + r2a + c) = make_float2(tf32r(acc[j][2] * i2), tf32r(acc[j][3] * i2));
        }
        __syncthreads();
    }
}

/* ============================================================ */
extern "C" void kernel_launch(void* const* d_in, const int* in_sizes, int n_in,
                              void* d_out, int out_size)
{
    const float* x  = (const float*)d_in[0];
    const float* W[4] = { (const float*)d_in[1], (const float*)d_in[2],
                          (const float*)d_in[3], (const float*)d_in[4] };
    float* out = (float*)d_out;

    float *qp, *kp, *vp, *xr, *wr;
    __nv_bfloat16 *qhp, *qlp, *khp, *klp, *vthp, *vtlp;
    cudaGetSymbolAddress((void**)&qp, g_q);
    cudaGetSymbolAddress((void**)&kp, g_k);
    cudaGetSymbolAddress((void**)&vp, g_v);
    cudaGetSymbolAddress((void**)&xr, g_xr);
    cudaGetSymbolAddress((void**)&wr, g_wr);
    cudaGetSymbolAddress((void**)&qhp, g_qh);
    cudaGetSymbolAddress((void**)&qlp, g_ql);
    cudaGetSymbolAddress((void**)&khp, g_kh);
    cudaGetSymbolAddress((void**)&klp, g_kl);
    cudaGetSymbolAddress((void**)&vthp, g_vth);
    cudaGetSymbolAddress((void**)&vtlp, g_vtl);

    static bool attr_done = false;
    if (!attr_done) {
        cudaFuncSetAttribute(gemm_tf32_kernel,
                             cudaFuncAttributeMaxDynamicSharedMemorySize, GEMM_SMEM);
        cudaFuncSetAttribute(attn_mma_kernel,
                             cudaFuncAttributeMaxDynamicSharedMemorySize, ATTN_SMEM);
        attr_done = true;
    }

    const size_t WSZ = (size_t)D_MODEL * D_MODEL;

    round_all_kernel<<<8192, 256>>>(x, W[0], W[1], W[2], W[3], xr, wr);

    const dim3 gg(D_MODEL / 128, M_TOT / 128);   /* (8, 32) */

    gemm_tf32_kernel<<<gg, 512, GEMM_SMEM>>>(xr, wr + 0 * WSZ, qp, M_TOT, D_MODEL, D_MODEL);
    gemm_tf32_kernel<<<gg, 512, GEMM_SMEM>>>(xr, wr + 1 * WSZ, kp, M_TOT, D_MODEL, D_MODEL);
    gemm_tf32_kernel<<<gg, 512, GEMM_SMEM>>>(xr, wr + 2 * WSZ, vp, M_TOT, D_MODEL, D_MODEL);

    rope2_kernel<<<M_TOT / 8, 256>>>(qp, kp, qhp, qlp, khp, klp);
    vtrans_kernel<<<dim3(SEQ / 64, BATCH * N_HEADS), 256>>>(vp, vthp, vtlp);

    attn_mma_kernel<<<dim3(NQB / 2, BATCH * N_HEADS), 256, ATTN_SMEM>>>(
        qhp, qlp, khp, klp, vthp, vtlp, qp);

    gemm_tf32_kernel<<<gg, 512, GEMM_SMEM>>>(qp, wr + 3 * WSZ, out, M_TOT, D_MODEL, D_MODEL);
}

// round 13
// speedup vs baseline: 1.1528x; 1.1528x over previous
#include <cuda_runtime.h>
#include <cuda_bf16.h>
#include <math.h>
#include <stdint.h>

#define D_MODEL 1024
#define N_HEADS 16
#define HEAD_DIM 64
#define BATCH 2
#define SEQ 2048
#define M_TOT (BATCH * SEQ)   /* 4096 */

/* ---- scratch (allocation-free: __device__ globals) ---- */
__device__ float g_q[(size_t)M_TOT * D_MODEL];   /* q proj, later attn out */
__device__ float g_k[(size_t)M_TOT * D_MODEL];
__device__ float g_v[(size_t)M_TOT * D_MODEL];
__device__ float g_xr[(size_t)M_TOT * D_MODEL];          /* tf32-rounded x */
__device__ float g_wr[4][(size_t)D_MODEL * D_MODEL];     /* tf32-rounded W */
__device__ float g_qr[(size_t)M_TOT * D_MODEL];          /* rope'd q (tf32) */
__device__ float g_kr[(size_t)M_TOT * D_MODEL];          /* rope'd k (tf32) */
__device__ float g_vt[(size_t)M_TOT * D_MODEL];          /* V^T [bh][d][S], key-permuted */

__device__ __forceinline__ uint32_t smem_to_u32(const void* p) {
    uint32_t a;
    asm("{ .reg .u64 t; cvta.to.shared.u64 t, %1; cvt.u32.u64 %0, t; }" : "=r"(a) : "l"(p));
    return a;
}

#define LDSM_X4(r0, r1, r2, r3, addr) \
    asm volatile("ldmatrix.sync.aligned.m8n8.x4.shared.b16 {%0,%1,%2,%3}, [%4];" \
                 : "=r"(r0), "=r"(r1), "=r"(r2), "=r"(r3) : "r"(addr))

#define MMA_TF32(c, a, b) \
    asm volatile("mma.sync.aligned.m16n8k8.row.col.f32.tf32.tf32.f32 " \
                 "{%0,%1,%2,%3},{%4,%5,%6,%7},{%8,%9},{%0,%1,%2,%3};" \
                 : "+f"((c)[0]), "+f"((c)[1]), "+f"((c)[2]), "+f"((c)[3]) \
                 : "r"((a)[0]), "r"((a)[1]), "r"((a)[2]), "r"((a)[3]), \
                   "r"((b)[0]), "r"((b)[1]))

#define CP_ASYNC16(saddr, gptr) \
    asm volatile("cp.async.cg.shared.global [%0], [%1], 16;" \
                 :: "r"(saddr), "l"(gptr) : "memory")
#define CP_COMMIT() asm volatile("cp.async.commit_group;" ::: "memory")
#define CP_WAIT0()  asm volatile("cp.async.wait_group 0;" ::: "memory")
#define CP_WAIT1()  asm volatile("cp.async.wait_group 1;" ::: "memory")

__device__ __forceinline__ float tf32r(float x) {
    uint32_t r;
    asm("cvt.rna.tf32.f32 %0, %1;" : "=r"(r) : "f"(x));
    return __uint_as_float(r);
}

/* ============================================================
 * Merged fp32 -> tf32 rounding for x + all 4 weights (1 launch).
 * ============================================================ */
__global__ void __launch_bounds__(256)
round_all_kernel(const float* __restrict__ x,
                 const float* __restrict__ w0, const float* __restrict__ w1,
                 const float* __restrict__ w2, const float* __restrict__ w3,
                 float* __restrict__ xr, float* __restrict__ wr)
{
    const int b = blockIdx.x;
    const float* src;
    float* dst;
    int lb;
    if (b < 4096) { src = x; dst = xr; lb = b; }
    else {
        const int r = b - 4096;
        const int w = r >> 10;
        src = (w == 0) ? w0 : (w == 1) ? w1 : (w == 2) ? w2 : w3;
        dst = wr + (size_t)w * D_MODEL * D_MODEL;
        lb = r & 1023;
    }
    const size_t i = ((size_t)lb * 256 + threadIdx.x) * 4;
    float4 v = *(const float4*)(src + i);
    v.x = tf32r(v.x); v.y = tf32r(v.y); v.z = tf32r(v.z); v.w = tf32r(v.w);
    *(float4*)(dst + i) = v;
}

/* ============================================================
 * tf32 single-pass GEMM (round-10 config: best measured).
 * CTA 128x128, BK=32, 8 warps (2x4), warp tile 64x32,
 * mma.m16n8k8, 2-stage cp.async. Scalar fragment loads.
 * ============================================================ */
#define TPAD 144
#define TTILE (128 * TPAD)
#define TSTG (2 * TTILE)
#define GEMM_SMEM (2 * TSTG)  /* 73728 */

__global__ void __launch_bounds__(256, 2)
gemm_tf32_kernel(const float* __restrict__ A, const float* __restrict__ B,
                 float* __restrict__ C, int M, int N, int K)
{
    extern __shared__ __align__(16) char smem[];
    const uint32_t su = smem_to_u32(smem);

    const int tid    = threadIdx.x;
    const int lane   = tid & 31;
    const int wid    = tid >> 5;
    const int warp_m = wid >> 2;
    const int warp_n = wid & 3;
    const int m0 = blockIdx.y * 128;
    const int n0 = blockIdx.x * 128;

    const int nchunks = K / 32;

    auto issue_stage = [&](int s, int i) {
        const uint32_t sb = su + s * TSTG;
        #pragma unroll
        for (int t = 0; t < 4; t++) {
            const int idx = tid + t * 256;
            const int row = idx >> 3, c = idx & 7;
            const uint32_t so = (uint32_t)row * TPAD + c * 16;
            const size_t ga = (size_t)(m0 + row) * K + i * 32 + c * 4;
            const size_t gb = (size_t)(n0 + row) * K + i * 32 + c * 4;
            CP_ASYNC16(sb + so, A + ga);
            CP_ASYNC16(sb + TTILE + so, B + gb);
        }
        CP_COMMIT();
    };

    issue_stage(0, 0);

    const int arow = warp_m * 64 + (lane >> 2);
    const int brow = warp_n * 32 + (lane >> 2);
    const int coff = (lane & 3) * 4;

    float acc[4][4][4] = {};

    for (int i = 0; i < nchunks; i++) {
        const int s = i & 1;
        if (i + 1 < nchunks) { issue_stage(s ^ 1, i + 1); CP_WAIT1(); }
        else                 { CP_WAIT0(); }
        __syncthreads();

        const char* sa  = smem + s * TSTG;
        const char* sbb = smem + s * TSTG + TTILE;

        #pragma unroll
        for (int ks = 0; ks < 4; ks++) {
            uint32_t af[4][4];
            #pragma unroll
            for (int mt = 0; mt < 4; mt++) {
                const char* ab = sa + (arow + mt * 16) * TPAD + coff + ks * 32;
                af[mt][0] = *(const uint32_t*)(ab);
                af[mt][1] = *(const uint32_t*)(ab + 8 * TPAD);
                af[mt][2] = *(const uint32_t*)(ab + 16);
                af[mt][3] = *(const uint32_t*)(ab + 8 * TPAD + 16);
            }
            uint32_t bf[4][2];
            #pragma unroll
            for (int nt = 0; nt < 4; nt++) {
                const char* bb = sbb + (brow + nt * 8) * TPAD + coff + ks * 32;
                bf[nt][0] = *(const uint32_t*)(bb);
                bf[nt][1] = *(const uint32_t*)(bb + 16);
            }
            #pragma unroll
            for (int mt = 0; mt < 4; mt++)
                #pragma unroll
                for (int nt = 0; nt < 4; nt++)
                    MMA_TF32(acc[mt][nt], af[mt], bf[nt]);
        }
        __syncthreads();
    }

    #pragma unroll
    for (int mt = 0; mt < 4; mt++) {
        const int m = m0 + warp_m * 64 + mt * 16 + (lane >> 2);
        #pragma unroll
        for (int nt = 0; nt < 4; nt++) {
            const int n = n0 + warp_n * 32 + nt * 8 + (lane & 3) * 2;
            *(float2*)(C + (size_t)m * N + n) =
                make_float2(acc[mt][nt][0], acc[mt][nt][1]);
            *(float2*)(C + (size_t)(m + 8) * N + n) =
                make_float2(acc[mt][nt][2], acc[mt][nt][3]);
        }
    }
}

/* ============================================================
 * Fused RoPE for Q and K -> tf32-rounded fp32.
 * ============================================================ */
__global__ void __launch_bounds__(256)
rope2_kernel(const float* __restrict__ q, const float* __restrict__ k,
             float* __restrict__ qr, float* __restrict__ kr)
{
    __shared__ float invf[32];
    const int tid = threadIdx.x;
    if (tid < 32) invf[tid] = (float)pow(10000.0, -(double)tid / 32.0);
    __syncthreads();

    const int bs   = blockIdx.x * 8 + (tid >> 5);
    const int lane = tid & 31;
    const int pos  = bs & (SEQ - 1);

    float s1, c1, s2, c2;
    sincosf((float)pos * invf[(2 * lane) & 31],     &s1, &c1);
    sincosf((float)pos * invf[(2 * lane + 1) & 31], &s2, &c2);

    const size_t base = (size_t)bs * D_MODEL;
    #pragma unroll
    for (int h = 0; h < N_HEADS; h++) {
        const size_t ro = base + h * 64;
        {
            float x0 = q[ro + 2 * lane], x1 = q[ro + 2 * lane + 1];
            qr[ro + lane]      = tf32r((x0 * c1 - x1 * s1) * 0.125f);
            qr[ro + 32 + lane] = tf32r((x0 * s2 + x1 * c2) * 0.125f);
        }
        {
            float x0 = k[ro + 2 * lane], x1 = k[ro + 2 * lane + 1];
            kr[ro + lane]      = tf32r(x0 * c1 - x1 * s1);
            kr[ro + 32 + lane] = tf32r(x0 * s2 + x1 * c2);
        }
    }
}

/* ============================================================
 * V transpose -> vt [bh][d][S] fp32 (tf32-rounded), with keys
 * PERMUTED within each 8-group: position p holds key
 * (p<4 ? 2p : 2p-7), so the S accumulator quad is directly the
 * tf32 PV A-fragment (no shuffles).
 * ============================================================ */
__global__ void __launch_bounds__(256)
vtrans_kernel(const float* __restrict__ v, float* __restrict__ vt)
{
    __shared__ float t[64][65];
    const int sblk = blockIdx.x;
    const int bh   = blockIdx.y;
    const int tid  = threadIdx.x;

    {
        const int row = tid >> 2;
        const int c0  = (tid & 3) * 16;
        const size_t gaddr = ((size_t)(bh >> 4) * SEQ + sblk * 64 + row) * D_MODEL
                           + (bh & 15) * 64 + c0;
        #pragma unroll
        for (int f = 0; f < 4; f++) {
            float4 vv = *(const float4*)(v + gaddr + f * 4);
            t[row][c0 + f * 4 + 0] = vv.x; t[row][c0 + f * 4 + 1] = vv.y;
            t[row][c0 + f * 4 + 2] = vv.z; t[row][c0 + f * 4 + 3] = vv.w;
        }
    }
    __syncthreads();

    const int d  = tid >> 2;
    const int k0 = (tid & 3) * 16;
    float out[16];
    #pragma unroll
    for (int g = 0; g < 2; g++)
        #pragma unroll
        for (int s = 0; s < 8; s++) {
            const int pos = (s >> 1) | ((s & 1) << 2);   /* key s -> slot */
            out[g * 8 + pos] = tf32r(t[k0 + g * 8 + s][d]);
        }
    const size_t dst = ((size_t)bh * 64 + d) * SEQ + sblk * 64 + k0;
    #pragma unroll
    for (int f = 0; f < 4; f++)
        *(float4*)(vt + dst + f * 4) = *(float4*)(out + f * 4);
}

/* ============================================================
 * Flash attention, causal, SINGLE-PASS tf32 mma (m16n8k8).
 * Block = 128 q-rows of one (b,h), 8 warps, qb-paired balance.
 * Q/K/Vt fp32 in smem (pitch 272B); P->A frag via register
 * renaming (V key-permuted); cp.async double-buffered K/V.
 * ============================================================ */
#define AQP 272               /* 64 floats + 16B pad */
#define AQT (128 * AQP)       /* 34816 */
#define AKT (64 * AQP)        /* 17408 */
#define ASTG (2 * AKT)        /* K + V = 34816 */
#define ATTN_SMEM (AQT + 2 * ASTG)   /* 104448 */
#define NQB (SEQ / 128)       /* 16 */

__global__ void __launch_bounds__(256, 2)
attn_mma_kernel(const float* __restrict__ qr, const float* __restrict__ kr,
                const float* __restrict__ vt, float* __restrict__ o)
{
    extern __shared__ __align__(16) char sm[];
    const uint32_t su = smem_to_u32(sm);

    const int bh   = blockIdx.y;
    const int tid  = threadIdx.x;
    const int lane = tid & 31;
    const int wid  = tid >> 5;

    const int b = bh >> 4, h = bh & 15;
    const size_t qkrow0 = ((size_t)b * SEQ) * D_MODEL + (size_t)h * 64;
    const size_t vtrow0 = ((size_t)bh * 64) * SEQ;

    const uint32_t a_ld = su + (uint32_t)(wid * 16 + (lane & 15)) * AQP + (lane >> 4) * 16;
    const uint32_t t_ld = su + AQT + (uint32_t)(lane & 15) * AQP + (lane >> 4) * 16;

    auto issue_stage = [&](int s, int kb) {
        const uint32_t sb = su + AQT + s * ASTG;
        #pragma unroll
        for (int i = 0; i < 4; i++) {
            const int idx = tid + i * 256;          /* 0..1023 */
            const int row = idx >> 4, c = idx & 15;
            const uint32_t so = (uint32_t)row * AQP + c * 16;
            const size_t gk = qkrow0 + (size_t)(kb * 64 + row) * D_MODEL + c * 4;
            const size_t gv = vtrow0 + (size_t)row * SEQ + kb * 64 + c * 4;
            CP_ASYNC16(sb + so, kr + gk);
            CP_ASYNC16(sb + AKT + so, vt + gv);
        }
        CP_COMMIT();
    };

    #pragma unroll 1
    for (int qi = 0; qi < 2; qi++) {
        const int qb = (qi == 0) ? blockIdx.x : (NQB - 1 - blockIdx.x);

        /* load Q tile: 128 rows x 256B */
        {
            #pragma unroll
            for (int i = 0; i < 8; i++) {
                const int idx = tid + i * 256;      /* 0..2047 */
                const int row = idx >> 4, c = idx & 15;
                const size_t g = qkrow0 + (size_t)(qb * 128 + row) * D_MODEL + c * 4;
                *(uint4*)(sm + (size_t)row * AQP + c * 16) = *(const uint4*)(qr + g);
            }
        }

        const int nkb = 2 * qb + 2;
        issue_stage(0, 0);

        float acc[8][4] = {};
        float mo1 = -1e30f, mo2 = -1e30f, l1 = 0.0f, l2 = 0.0f;
        const int q1g = qb * 128 + wid * 16 + (lane >> 2);
        const int warp_qmax = qb * 128 + wid * 16 + 15;

        for (int kb = 0; kb < nkb; kb++) {
            const int s = kb & 1;
            if (kb + 1 < nkb) { issue_stage(s ^ 1, kb + 1); CP_WAIT1(); }
            else              { CP_WAIT0(); }
            __syncthreads();

            const bool tile_active = (kb * 64 <= warp_qmax);

            if (tile_active) {
                const uint32_t k_ld = t_ld + s * ASTG;
                const uint32_t v_ld = k_ld + AKT;

                /* S = Q @ K^T (tf32, single pass) */
                float sc[8][4] = {};
                #pragma unroll
                for (int ks = 0; ks < 8; ks++) {
                    uint32_t af[4];
                    LDSM_X4(af[0], af[1], af[2], af[3], a_ld + ks * 32);
                    #pragma unroll
                    for (int nb = 0; nb < 4; nb++) {
                        if (kb * 64 + nb * 16 > warp_qmax) continue;
                        uint32_t r0, r1, r2, r3;
                        LDSM_X4(r0, r1, r2, r3, k_ld + nb * 16 * AQP + ks * 32);
                        uint32_t be[2] = {r0, r2}, bo[2] = {r1, r3};
                        MMA_TF32(sc[2 * nb],     af, be);
                        MMA_TF32(sc[2 * nb + 1], af, bo);
                    }
                }

                /* causal mask on partial tiles */
                if (kb * 64 + 63 > qb * 128 + wid * 16) {
                    #pragma unroll
                    for (int j = 0; j < 8; j++) {
                        const int c = kb * 64 + j * 8 + (lane & 3) * 2;
                        if (c     > q1g)     sc[j][0] = -1e30f;
                        if (c + 1 > q1g)     sc[j][1] = -1e30f;
                        if (c     > q1g + 8) sc[j][2] = -1e30f;
                        if (c + 1 > q1g + 8) sc[j][3] = -1e30f;
                    }
                }

                /* online softmax */
                float m1 = -1e30f, m2 = -1e30f;
                #pragma unroll
                for (int j = 0; j < 8; j++) {
                    m1 = fmaxf(m1, fmaxf(sc[j][0], sc[j][1]));
                    m2 = fmaxf(m2, fmaxf(sc[j][2], sc[j][3]));
                }
                m1 = fmaxf(m1, __shfl_xor_sync(0xffffffffu, m1, 1));
                m1 = fmaxf(m1, __shfl_xor_sync(0xffffffffu, m1, 2));
                m2 = fmaxf(m2, __shfl_xor_sync(0xffffffffu, m2, 1));
                m2 = fmaxf(m2, __shfl_xor_sync(0xffffffffu, m2, 2));
                const float mn1 = fmaxf(mo1, m1), mn2 = fmaxf(mo2, m2);
                const float sc1 = __expf(mo1 - mn1), sc2 = __expf(mo2 - mn2);
                float sum1 = 0.0f, sum2 = 0.0f;
                #pragma unroll
                for (int j = 0; j < 8; j++) {
                    sc[j][0] = __expf(sc[j][0] - mn1); sum1 += sc[j][0];
                    sc[j][1] = __expf(sc[j][1] - mn1); sum1 += sc[j][1];
                    sc[j][2] = __expf(sc[j][2] - mn2); sum2 += sc[j][2];
                    sc[j][3] = __expf(sc[j][3] - mn2); sum2 += sc[j][3];
                }
                sum1 += __shfl_xor_sync(0xffffffffu, sum1, 1);
                sum1 += __shfl_xor_sync(0xffffffffu, sum1, 2);
                sum2 += __shfl_xor_sync(0xffffffffu, sum2, 1);
                sum2 += __shfl_xor_sync(0xffffffffu, sum2, 2);
                l1 = l1 * sc1 + sum1; l2 = l2 * sc2 + sum2;
                mo1 = mn1; mo2 = mn2;
                #pragma unroll
                for (int j = 0; j < 8; j++) {
                    acc[j][0] *= sc1; acc[j][1] *= sc1;
                    acc[j][2] *= sc2; acc[j][3] *= sc2;
                }

                /* O += P @ V: P regs ARE the tf32 A-fragment (V key-permuted) */
                #pragma unroll
                for (int ks = 0; ks < 8; ks++) {
                    if (kb * 64 + ks * 8 > warp_qmax) continue;
                    uint32_t pa[4];
                    pa[0] = __float_as_uint(sc[ks][0]);
                    pa[1] = __float_as_uint(sc[ks][2]);
                    pa[2] = __float_as_uint(sc[ks][1]);
                    pa[3] = __float_as_uint(sc[ks][3]);
                    #pragma unroll
                    for (int nb = 0; nb < 4; nb++) {
                        uint32_t r0, r1, r2, r3;
                        LDSM_X4(r0, r1, r2, r3, v_ld + nb * 16 * AQP + ks * 32);
                        uint32_t be[2] = {r0, r2}, bo[2] = {r1, r3};
                        MMA_TF32(acc[2 * nb],     pa, be);
                        MMA_TF32(acc[2 * nb + 1], pa, bo);
                    }
                }
            }
            __syncthreads();
        }

        /* epilogue: normalize, tf32-round, store fp32 */
        const float i1 = 1.0f / l1, i2 = 1.0f / l2;
        const size_t r1a = qkrow0 + (size_t)(qb * 128 + wid * 16 + (lane >> 2)) * D_MODEL;
        const size_t r2a = r1a + 8 * D_MODEL;
        #pragma unroll
        for (int j = 0; j < 8; j++) {
            const int c = j * 8 + (lane & 3) * 2;
            *(float2*)(o + r1a + c) = make_float2(tf32r(acc[j][0] * i1), tf32r(acc[j][1] * i1));
            *(float2*)(o + r2a + c) = make_float2(tf32r(acc[j][2] * i2), tf32r(acc[j][3] * i2));
        }
        __syncthreads();
    }
}

/* ============================================================ */
extern "C" void kernel_launch(void* const* d_in, const int* in_sizes, int n_in,
                              void* d_out, int out_size)
{
    const float* x  = (const float*)d_in[0];
    const float* W[4] = { (const float*)d_in[1], (const float*)d_in[2],
                          (const float*)d_in[3], (const float*)d_in[4] };
    float* out = (float*)d_out;

    float *qp, *kp, *vp, *xr, *wr, *qrp, *krp, *vtp;
    cudaGetSymbolAddress((void**)&qp, g_q);
    cudaGetSymbolAddress((void**)&kp, g_k);
    cudaGetSymbolAddress((void**)&vp, g_v);
    cudaGetSymbolAddress((void**)&xr, g_xr);
    cudaGetSymbolAddress((void**)&wr, g_wr);
    cudaGetSymbolAddress((void**)&qrp, g_qr);
    cudaGetSymbolAddress((void**)&krp, g_kr);
    cudaGetSymbolAddress((void**)&vtp, g_vt);

    static bool attr_done = false;
    if (!attr_done) {
        cudaFuncSetAttribute(gemm_tf32_kernel,
                             cudaFuncAttributeMaxDynamicSharedMemorySize, GEMM_SMEM);
        cudaFuncSetAttribute(attn_mma_kernel,
                             cudaFuncAttributeMaxDynamicSharedMemorySize, ATTN_SMEM);
        attr_done = true;
    }

    const size_t WSZ = (size_t)D_MODEL * D_MODEL;

    round_all_kernel<<<8192, 256>>>(x, W[0], W[1], W[2], W[3], xr, wr);

    const dim3 gg(D_MODEL / 128, M_TOT / 128);   /* (8, 32) */

    gemm_tf32_kernel<<<gg, 256, GEMM_SMEM>>>(xr, wr + 0 * WSZ, qp, M_TOT, D_MODEL, D_MODEL);
    gemm_tf32_kernel<<<gg, 256, GEMM_SMEM>>>(xr, wr + 1 * WSZ, kp, M_TOT, D_MODEL, D_MODEL);
    gemm_tf32_kernel<<<gg, 256, GEMM_SMEM>>>(xr, wr + 2 * WSZ, vp, M_TOT, D_MODEL, D_MODEL);

    rope2_kernel<<<M_TOT / 8, 256>>>(qp, kp, qrp, krp);
    vtrans_kernel<<<dim3(SEQ / 64, BATCH * N_HEADS), 256>>>(vp, vtp);

    attn_mma_kernel<<<dim3(NQB / 2, BATCH * N_HEADS), 256, ATTN_SMEM>>>(
        qrp, krp, vtp, qp);

    gemm_tf32_kernel<<<gg, 256, GEMM_SMEM>>>(qp, wr + 3 * WSZ, out, M_TOT, D_MODEL, D_MODEL);
}

// round 14
// speedup vs baseline: 1.8199x; 1.5786x over previous
#include <cuda_runtime.h>
#include <cuda_fp16.h>
#include <math.h>
#include <stdint.h>

#define D_MODEL 1024
#define N_HEADS 16
#define HEAD_DIM 64
#define BATCH 2
#define SEQ 2048
#define M_TOT (BATCH * SEQ)   /* 4096 */

/* ---- scratch (allocation-free: __device__ globals) ---- */
__device__ float g_q[(size_t)M_TOT * D_MODEL];
__device__ float g_k[(size_t)M_TOT * D_MODEL];
__device__ float g_v[(size_t)M_TOT * D_MODEL];
__device__ __half g_xh[(size_t)M_TOT * D_MODEL];
__device__ __half g_wh[4][(size_t)D_MODEL * D_MODEL];
__device__ __half g_qh[(size_t)M_TOT * D_MODEL];
__device__ __half g_kh[(size_t)M_TOT * D_MODEL];
__device__ __half g_vt[(size_t)M_TOT * D_MODEL];   /* V^T [bh][d][S] */
__device__ __half g_ao[(size_t)M_TOT * D_MODEL];   /* attn out, fp16 */

__device__ __forceinline__ uint32_t smem_to_u32(const void* p) {
    uint32_t a;
    asm("{ .reg .u64 t; cvta.to.shared.u64 t, %1; cvt.u32.u64 %0, t; }" : "=r"(a) : "l"(p));
    return a;
}

#define LDSM_X4(r0, r1, r2, r3, addr) \
    asm volatile("ldmatrix.sync.aligned.m8n8.x4.shared.b16 {%0,%1,%2,%3}, [%4];" \
                 : "=r"(r0), "=r"(r1), "=r"(r2), "=r"(r3) : "r"(addr))

#define MMA_FP16(c, a, b) \
    asm volatile("mma.sync.aligned.m16n8k16.row.col.f32.f16.f16.f32 " \
                 "{%0,%1,%2,%3},{%4,%5,%6,%7},{%8,%9},{%0,%1,%2,%3};" \
                 : "+f"((c)[0]), "+f"((c)[1]), "+f"((c)[2]), "+f"((c)[3]) \
                 : "r"((a)[0]), "r"((a)[1]), "r"((a)[2]), "r"((a)[3]), \
                   "r"((b)[0]), "r"((b)[1]))

#define CP_ASYNC16(saddr, gptr) \
    asm volatile("cp.async.cg.shared.global [%0], [%1], 16;" \
                 :: "r"(saddr), "l"(gptr) : "memory")
#define CP_COMMIT() asm volatile("cp.async.commit_group;" ::: "memory")
#define CP_WAIT0()  asm volatile("cp.async.wait_group 0;" ::: "memory")
#define CP_WAIT1()  asm volatile("cp.async.wait_group 1;" ::: "memory")

__device__ __forceinline__ uint32_t pk_h2(float a, float b) {
    __half2 h = __floats2half2_rn(a, b);
    return *(uint32_t*)&h;
}

/* ============================================================
 * Merged fp32 -> fp16 conversion for x + all 4 weights.
 * ============================================================ */
__global__ void __launch_bounds__(256)
convert_all_kernel(const float* __restrict__ x,
                   const float* __restrict__ w0, const float* __restrict__ w1,
                   const float* __restrict__ w2, const float* __restrict__ w3,
                   __half* __restrict__ xh, __half* __restrict__ wh)
{
    const int b = blockIdx.x;
    const float* src;
    __half* dst;
    int lb;
    if (b < 4096) { src = x; dst = xh; lb = b; }
    else {
        const int r = b - 4096;
        const int w = r >> 10;
        src = (w == 0) ? w0 : (w == 1) ? w1 : (w == 2) ? w2 : w3;
        dst = wh + (size_t)w * D_MODEL * D_MODEL;
        lb = r & 1023;
    }
    const size_t i = ((size_t)lb * 256 + threadIdx.x) * 4;
    float4 v = *(const float4*)(src + i);
    *(uint2*)(dst + i) = make_uint2(pk_h2(v.x, v.y), pk_h2(v.z, v.w));
}

/* ============================================================
 * fp16 single-pass GEMM: C[M,N] = A[M,K] @ B[N,K]^T, fp32 accum.
 * CTA 128x128, BK=32, 8 warps (2x4), warp tile 64x32,
 * mma.m16n8k16, cp.async double-buffered (round-3 layout).
 * ============================================================ */
#define SPITCH 80
#define TBYTES (128 * SPITCH)  /* 10240 */
#define GSTG (2 * TBYTES)      /* 20480 */
#define GEMM_SMEM (2 * GSTG)   /* 40960 */

__global__ void __launch_bounds__(256, 2)
gemm_fp16_kernel(const __half* __restrict__ A, const __half* __restrict__ B,
                 float* __restrict__ C, int M, int N, int K)
{
    extern __shared__ __align__(16) char smem[];
    const uint32_t su = smem_to_u32(smem);

    const int tid    = threadIdx.x;
    const int lane   = tid & 31;
    const int wid    = tid >> 5;
    const int warp_m = wid >> 2;
    const int warp_n = wid & 3;
    const int m0 = blockIdx.y * 128;
    const int n0 = blockIdx.x * 128;

    const int nchunks = K / 32;

    auto issue_stage = [&](int s, int i) {
        const uint32_t sb = su + s * GSTG;
        #pragma unroll
        for (int t = 0; t < 2; t++) {
            const int idx = tid + t * 256;          /* 0..511 */
            const int row = idx >> 2, c = idx & 3;
            const uint32_t so = (uint32_t)row * SPITCH + c * 16;
            const size_t ga = (size_t)(m0 + row) * K + i * 32 + c * 8;
            const size_t gb = (size_t)(n0 + row) * K + i * 32 + c * 8;
            CP_ASYNC16(sb + so, A + ga);
            CP_ASYNC16(sb + TBYTES + so, B + gb);
        }
        CP_COMMIT();
    };

    issue_stage(0, 0);

    const uint32_t a_ld = su + (uint32_t)(warp_m * 64 + (lane & 15)) * SPITCH + (lane >> 4) * 16;
    const uint32_t b_ld = su + TBYTES + (uint32_t)(warp_n * 32 + (lane & 15)) * SPITCH + (lane >> 4) * 16;

    float acc[4][4][4] = {};

    for (int i = 0; i < nchunks; i++) {
        const int s = i & 1;
        if (i + 1 < nchunks) { issue_stage(s ^ 1, i + 1); CP_WAIT1(); }
        else                 { CP_WAIT0(); }
        __syncthreads();

        const uint32_t stb = s * GSTG;
        #pragma unroll
        for (int ks = 0; ks < 2; ks++) {
            uint32_t af[4][4];
            #pragma unroll
            for (int mt = 0; mt < 4; mt++)
                LDSM_X4(af[mt][0], af[mt][1], af[mt][2], af[mt][3],
                        a_ld + stb + mt * 16 * SPITCH + ks * 32);
            uint32_t bf[4][2];
            #pragma unroll
            for (int nb = 0; nb < 2; nb++) {
                uint32_t r0, r1, r2, r3;
                LDSM_X4(r0, r1, r2, r3, b_ld + stb + nb * 16 * SPITCH + ks * 32);
                bf[nb * 2][0]     = r0; bf[nb * 2][1]     = r2;
                bf[nb * 2 + 1][0] = r1; bf[nb * 2 + 1][1] = r3;
            }
            #pragma unroll
            for (int mt = 0; mt < 4; mt++)
                #pragma unroll
                for (int nt = 0; nt < 4; nt++)
                    MMA_FP16(acc[mt][nt], af[mt], bf[nt]);
        }
        __syncthreads();
    }

    #pragma unroll
    for (int mt = 0; mt < 4; mt++) {
        const int m = m0 + warp_m * 64 + mt * 16 + (lane >> 2);
        #pragma unroll
        for (int nt = 0; nt < 4; nt++) {
            const int n = n0 + warp_n * 32 + nt * 8 + (lane & 3) * 2;
            *(float2*)(C + (size_t)m * N + n) =
                make_float2(acc[mt][nt][0], acc[mt][nt][1]);
            *(float2*)(C + (size_t)(m + 8) * N + n) =
                make_float2(acc[mt][nt][2], acc[mt][nt][3]);
        }
    }
}

/* ============================================================
 * Fused RoPE for Q and K -> fp16 (scale folded into Q).
 * ============================================================ */
__global__ void __launch_bounds__(256)
rope2_kernel(const float* __restrict__ q, const float* __restrict__ k,
             __half* __restrict__ qh, __half* __restrict__ kh)
{
    __shared__ float invf[32];
    const int tid = threadIdx.x;
    if (tid < 32) invf[tid] = (float)pow(10000.0, -(double)tid / 32.0);
    __syncthreads();

    const int bs   = blockIdx.x * 8 + (tid >> 5);
    const int lane = tid & 31;
    const int pos  = bs & (SEQ - 1);

    float s1, c1, s2, c2;
    sincosf((float)pos * invf[(2 * lane) & 31],     &s1, &c1);
    sincosf((float)pos * invf[(2 * lane + 1) & 31], &s2, &c2);

    const size_t base = (size_t)bs * D_MODEL;
    #pragma unroll
    for (int h = 0; h < N_HEADS; h++) {
        const size_t ro = base + h * 64;
        {
            float x0 = q[ro + 2 * lane], x1 = q[ro + 2 * lane + 1];
            qh[ro + lane]      = __float2half_rn((x0 * c1 - x1 * s1) * 0.125f);
            qh[ro + 32 + lane] = __float2half_rn((x0 * s2 + x1 * c2) * 0.125f);
        }
        {
            float x0 = k[ro + 2 * lane], x1 = k[ro + 2 * lane + 1];
            kh[ro + lane]      = __float2half_rn(x0 * c1 - x1 * s1);
            kh[ro + 32 + lane] = __float2half_rn(x0 * s2 + x1 * c2);
        }
    }
}

/* ============================================================
 * V transpose -> vt [bh][d][S] fp16 (natural key order).
 * ============================================================ */
__global__ void __launch_bounds__(256)
vtrans_kernel(const float* __restrict__ v, __half* __restrict__ vt)
{
    __shared__ float t[64][65];
    const int sblk = blockIdx.x;
    const int bh   = blockIdx.y;
    const int tid  = threadIdx.x;

    {
        const int row = tid >> 2;
        const int c0  = (tid & 3) * 16;
        const size_t gaddr = ((size_t)(bh >> 4) * SEQ + sblk * 64 + row) * D_MODEL
                           + (bh & 15) * 64 + c0;
        #pragma unroll
        for (int f = 0; f < 4; f++) {
            float4 vv = *(const float4*)(v + gaddr + f * 4);
            t[row][c0 + f * 4 + 0] = vv.x; t[row][c0 + f * 4 + 1] = vv.y;
            t[row][c0 + f * 4 + 2] = vv.z; t[row][c0 + f * 4 + 3] = vv.w;
        }
    }
    __syncthreads();

    const int d  = tid >> 2;
    const int k0 = (tid & 3) * 16;
    uint32_t out[8];
    #pragma unroll
    for (int p = 0; p < 8; p++)
        out[p] = pk_h2(t[k0 + 2 * p][d], t[k0 + 2 * p + 1][d]);
    const size_t dst = ((size_t)bh * 64 + d) * SEQ + sblk * 64 + k0;
    *(uint4*)(vt + dst)     = *(uint4*)(out);
    *(uint4*)(vt + dst + 8) = *(uint4*)(out + 4);
}

/* ============================================================
 * Flash attention, causal, single-pass fp16 mma (m16n8k16).
 * Block = 128 q-rows of one (b,h), 8 warps, qb-paired balance,
 * cp.async double-buffered K/V. Output fp16.
 * ============================================================ */
#define AQP 144
#define AQT (128 * AQP)        /* 18432 */
#define AKT (64 * AQP)         /* 9216 */
#define ASTG (2 * AKT)         /* K + V = 18432 */
#define ATTN_SMEM (AQT + 2 * ASTG)   /* 55296 */
#define NQB (SEQ / 128)        /* 16 */

__global__ void __launch_bounds__(256, 2)
attn_mma_kernel(const __half* __restrict__ qh, const __half* __restrict__ kh,
                const __half* __restrict__ vt, __half* __restrict__ o)
{
    extern __shared__ __align__(16) char sm[];
    const uint32_t su = smem_to_u32(sm);

    const int bh   = blockIdx.y;
    const int tid  = threadIdx.x;
    const int lane = tid & 31;
    const int wid  = tid >> 5;

    const int b = bh >> 4, h = bh & 15;
    const size_t qkrow0 = ((size_t)b * SEQ) * D_MODEL + (size_t)h * 64;
    const size_t vtrow0 = ((size_t)bh * 64) * SEQ;

    const uint32_t a_ld = su + (uint32_t)(wid * 16 + (lane & 15)) * AQP + (lane >> 4) * 16;
    const uint32_t t_ld = su + AQT + (uint32_t)(lane & 15) * AQP + (lane >> 4) * 16;

    auto issue_stage = [&](int s, int kb) {
        const uint32_t sb = su + AQT + s * ASTG;
        #pragma unroll
        for (int i = 0; i < 2; i++) {
            const int idx = tid + i * 256;          /* 0..511 */
            const int row = idx >> 3, c = idx & 7;
            const uint32_t so = (uint32_t)row * AQP + c * 16;
            const size_t gk = qkrow0 + (size_t)(kb * 64 + row) * D_MODEL + c * 8;
            const size_t gv = vtrow0 + (size_t)row * SEQ + kb * 64 + c * 8;
            CP_ASYNC16(sb + so, kh + gk);
            CP_ASYNC16(sb + AKT + so, vt + gv);
        }
        CP_COMMIT();
    };

    #pragma unroll 1
    for (int qi = 0; qi < 2; qi++) {
        const int qb = (qi == 0) ? blockIdx.x : (NQB - 1 - blockIdx.x);

        /* load Q tile: 128 rows x 128B */
        {
            #pragma unroll
            for (int i = 0; i < 4; i++) {
                const int idx = tid + i * 256;      /* 0..1023 */
                const int row = idx >> 3, c = idx & 7;
                const size_t g = qkrow0 + (size_t)(qb * 128 + row) * D_MODEL + c * 8;
                *(uint4*)(sm + (size_t)row * AQP + c * 16) = *(const uint4*)(qh + g);
            }
        }

        const int nkb = 2 * qb + 2;
        issue_stage(0, 0);

        float acc[8][4] = {};
        float mo1 = -1e30f, mo2 = -1e30f, l1 = 0.0f, l2 = 0.0f;
        const int q1g = qb * 128 + wid * 16 + (lane >> 2);
        const int warp_qmax = qb * 128 + wid * 16 + 15;

        for (int kb = 0; kb < nkb; kb++) {
            const int s = kb & 1;
            if (kb + 1 < nkb) { issue_stage(s ^ 1, kb + 1); CP_WAIT1(); }
            else              { CP_WAIT0(); }
            __syncthreads();

            const bool tile_active = (kb * 64 <= warp_qmax);

            if (tile_active) {
                const uint32_t k_ld = t_ld + s * ASTG;
                const uint32_t v_ld = k_ld + AKT;

                /* S = Q @ K^T */
                float sc[8][4] = {};
                #pragma unroll
                for (int ks = 0; ks < 4; ks++) {
                    uint32_t af[4];
                    LDSM_X4(af[0], af[1], af[2], af[3], a_ld + ks * 32);
                    #pragma unroll
                    for (int nb = 0; nb < 4; nb++) {
                        if (kb * 64 + nb * 16 > warp_qmax) continue;
                        uint32_t r0, r1, r2, r3;
                        LDSM_X4(r0, r1, r2, r3, k_ld + nb * 16 * AQP + ks * 32);
                        uint32_t be[2] = {r0, r2}, bo[2] = {r1, r3};
                        MMA_FP16(sc[2 * nb],     af, be);
                        MMA_FP16(sc[2 * nb + 1], af, bo);
                    }
                }

                /* causal mask */
                if (kb * 64 + 63 > qb * 128 + wid * 16) {
                    #pragma unroll
                    for (int j = 0; j < 8; j++) {
                        const int c = kb * 64 + j * 8 + (lane & 3) * 2;
                        if (c     > q1g)     sc[j][0] = -1e30f;
                        if (c + 1 > q1g)     sc[j][1] = -1e30f;
                        if (c     > q1g + 8) sc[j][2] = -1e30f;
                        if (c + 1 > q1g + 8) sc[j][3] = -1e30f;
                    }
                }

                /* online softmax */
                float m1 = -1e30f, m2 = -1e30f;
                #pragma unroll
                for (int j = 0; j < 8; j++) {
                    m1 = fmaxf(m1, fmaxf(sc[j][0], sc[j][1]));
                    m2 = fmaxf(m2, fmaxf(sc[j][2], sc[j][3]));
                }
                m1 = fmaxf(m1, __shfl_xor_sync(0xffffffffu, m1, 1));
                m1 = fmaxf(m1, __shfl_xor_sync(0xffffffffu, m1, 2));
                m2 = fmaxf(m2, __shfl_xor_sync(0xffffffffu, m2, 1));
                m2 = fmaxf(m2, __shfl_xor_sync(0xffffffffu, m2, 2));
                const float mn1 = fmaxf(mo1, m1), mn2 = fmaxf(mo2, m2);
                const float sc1 = __expf(mo1 - mn1), sc2 = __expf(mo2 - mn2);
                float sum1 = 0.0f, sum2 = 0.0f;
                #pragma unroll
                for (int j = 0; j < 8; j++) {
                    sc[j][0] = __expf(sc[j][0] - mn1); sum1 += sc[j][0];
                    sc[j][1] = __expf(sc[j][1] - mn1); sum1 += sc[j][1];
                    sc[j][2] = __expf(sc[j][2] - mn2); sum2 += sc[j][2];
                    sc[j][3] = __expf(sc[j][3] - mn2); sum2 += sc[j][3];
                }
                sum1 += __shfl_xor_sync(0xffffffffu, sum1, 1);
                sum1 += __shfl_xor_sync(0xffffffffu, sum1, 2);
                sum2 += __shfl_xor_sync(0xffffffffu, sum2, 1);
                sum2 += __shfl_xor_sync(0xffffffffu, sum2, 2);
                l1 = l1 * sc1 + sum1; l2 = l2 * sc2 + sum2;
                mo1 = mn1; mo2 = mn2;
                #pragma unroll
                for (int j = 0; j < 8; j++) {
                    acc[j][0] *= sc1; acc[j][1] *= sc1;
                    acc[j][2] *= sc2; acc[j][3] *= sc2;
                }

                /* O += P @ V: P packed from adjacent n-tile accumulators */
                #pragma unroll
                for (int kt = 0; kt < 4; kt++) {
                    if (kb * 64 + kt * 16 > warp_qmax) continue;
                    uint32_t pa[4];
                    pa[0] = pk_h2(sc[2 * kt][0],     sc[2 * kt][1]);
                    pa[1] = pk_h2(sc[2 * kt][2],     sc[2 * kt][3]);
                    pa[2] = pk_h2(sc[2 * kt + 1][0], sc[2 * kt + 1][1]);
                    pa[3] = pk_h2(sc[2 * kt + 1][2], sc[2 * kt + 1][3]);
                    #pragma unroll
                    for (int nb = 0; nb < 4; nb++) {
                        uint32_t r0, r1, r2, r3;
                        LDSM_X4(r0, r1, r2, r3, v_ld + nb * 16 * AQP + kt * 32);
                        uint32_t be[2] = {r0, r2}, bo[2] = {r1, r3};
                        MMA_FP16(acc[2 * nb],     pa, be);
                        MMA_FP16(acc[2 * nb + 1], pa, bo);
                    }
                }
            }
            __syncthreads();
        }

        /* epilogue: normalize, store fp16 */
        const float i1 = 1.0f / l1, i2 = 1.0f / l2;
        const size_t r1a = qkrow0 + (size_t)(qb * 128 + wid * 16 + (lane >> 2)) * D_MODEL;
        const size_t r2a = r1a + 8 * D_MODEL;
        #pragma unroll
        for (int j = 0; j < 8; j++) {
            const int c = j * 8 + (lane & 3) * 2;
            *(uint32_t*)(o + r1a + c) = pk_h2(acc[j][0] * i1, acc[j][1] * i1);
            *(uint32_t*)(o + r2a + c) = pk_h2(acc[j][2] * i2, acc[j][3] * i2);
        }
        __syncthreads();
    }
}

/* ============================================================ */
extern "C" void kernel_launch(void* const* d_in, const int* in_sizes, int n_in,
                              void* d_out, int out_size)
{
    const float* x  = (const float*)d_in[0];
    const float* W[4] = { (const float*)d_in[1], (const float*)d_in[2],
                          (const float*)d_in[3], (const float*)d_in[4] };
    float* out = (float*)d_out;

    float *qp, *kp, *vp;
    __half *xh, *wh, *qhp, *khp, *vtp, *aop;
    cudaGetSymbolAddress((void**)&qp, g_q);
    cudaGetSymbolAddress((void**)&kp, g_k);
    cudaGetSymbolAddress((void**)&vp, g_v);
    cudaGetSymbolAddress((void**)&xh, g_xh);
    cudaGetSymbolAddress((void**)&wh, g_wh);
    cudaGetSymbolAddress((void**)&qhp, g_qh);
    cudaGetSymbolAddress((void**)&khp, g_kh);
    cudaGetSymbolAddress((void**)&vtp, g_vt);
    cudaGetSymbolAddress((void**)&aop, g_ao);

    static bool attr_done = false;
    if (!attr_done) {
        cudaFuncSetAttribute(gemm_fp16_kernel,
                             cudaFuncAttributeMaxDynamicSharedMemorySize, GEMM_SMEM);
        cudaFuncSetAttribute(attn_mma_kernel,
                             cudaFuncAttributeMaxDynamicSharedMemorySize, ATTN_SMEM);
        attr_done = true;
    }

    const size_t WSZ = (size_t)D_MODEL * D_MODEL;

    convert_all_kernel<<<8192, 256>>>(x, W[0], W[1], W[2], W[3], xh, wh);

    const dim3 gg(D_MODEL / 128, M_TOT / 128);   /* (8, 32) */

    gemm_fp16_kernel<<<gg, 256, GEMM_SMEM>>>(xh, wh + 0 * WSZ, qp, M_TOT, D_MODEL, D_MODEL);
    gemm_fp16_kernel<<<gg, 256, GEMM_SMEM>>>(xh, wh + 1 * WSZ, kp, M_TOT, D_MODEL, D_MODEL);
    gemm_fp16_kernel<<<gg, 256, GEMM_SMEM>>>(xh, wh + 2 * WSZ, vp, M_TOT, D_MODEL, D_MODEL);

    rope2_kernel<<<M_TOT / 8, 256>>>(qp, kp, qhp, khp);
    vtrans_kernel<<<dim3(SEQ / 64, BATCH * N_HEADS), 256>>>(vp, vtp);

    attn_mma_kernel<<<dim3(NQB / 2, BATCH * N_HEADS), 256, ATTN_SMEM>>>(
        qhp, khp, vtp, aop);

    gemm_fp16_kernel<<<gg, 256, GEMM_SMEM>>>(aop, wh + 3 * WSZ, out, M_TOT, D_MODEL, D_MODEL);
}

// round 15
// speedup vs baseline: 2.0686x; 1.1367x over previous
#include <cuda_runtime.h>
#include <cuda_fp16.h>
#include <math.h>
#include <stdint.h>

#define D_MODEL 1024
#define N_HEADS 16
#define HEAD_DIM 64
#define BATCH 2
#define SEQ 2048
#define M_TOT (BATCH * SEQ)   /* 4096 */

/* ---- scratch (allocation-free: __device__ globals) ---- */
__device__ float g_q[(size_t)M_TOT * D_MODEL];
__device__ float g_k[(size_t)M_TOT * D_MODEL];
__device__ float g_v[(size_t)M_TOT * D_MODEL];
__device__ __half g_xh[(size_t)M_TOT * D_MODEL];
__device__ __half g_wh[4][(size_t)D_MODEL * D_MODEL];
__device__ __half g_qh[(size_t)M_TOT * D_MODEL];
__device__ __half g_kh[(size_t)M_TOT * D_MODEL];
__device__ __half g_vt[(size_t)M_TOT * D_MODEL];   /* V^T [bh][d][S] */
__device__ __half g_ao[(size_t)M_TOT * D_MODEL];   /* attn out, fp16 */

__device__ __forceinline__ uint32_t smem_to_u32(const void* p) {
    uint32_t a;
    asm("{ .reg .u64 t; cvta.to.shared.u64 t, %1; cvt.u32.u64 %0, t; }" : "=r"(a) : "l"(p));
    return a;
}

#define LDSM_X4(r0, r1, r2, r3, addr) \
    asm volatile("ldmatrix.sync.aligned.m8n8.x4.shared.b16 {%0,%1,%2,%3}, [%4];" \
                 : "=r"(r0), "=r"(r1), "=r"(r2), "=r"(r3) : "r"(addr))

#define MMA_FP16(c, a, b) \
    asm volatile("mma.sync.aligned.m16n8k16.row.col.f32.f16.f16.f32 " \
                 "{%0,%1,%2,%3},{%4,%5,%6,%7},{%8,%9},{%0,%1,%2,%3};" \
                 : "+f"((c)[0]), "+f"((c)[1]), "+f"((c)[2]), "+f"((c)[3]) \
                 : "r"((a)[0]), "r"((a)[1]), "r"((a)[2]), "r"((a)[3]), \
                   "r"((b)[0]), "r"((b)[1]))

#define CP_ASYNC16(saddr, gptr) \
    asm volatile("cp.async.cg.shared.global [%0], [%1], 16;" \
                 :: "r"(saddr), "l"(gptr) : "memory")
#define CP_COMMIT() asm volatile("cp.async.commit_group;" ::: "memory")
#define CP_WAIT0()  asm volatile("cp.async.wait_group 0;" ::: "memory")
#define CP_WAIT1()  asm volatile("cp.async.wait_group 1;" ::: "memory")

__device__ __forceinline__ uint32_t pk_h2(float a, float b) {
    __half2 h = __floats2half2_rn(a, b);
    return *(uint32_t*)&h;
}

/* ============================================================
 * Merged fp32 -> fp16 conversion for x + all 4 weights.
 * ============================================================ */
__global__ void __launch_bounds__(256)
convert_all_kernel(const float* __restrict__ x,
                   const float* __restrict__ w0, const float* __restrict__ w1,
                   const float* __restrict__ w2, const float* __restrict__ w3,
                   __half* __restrict__ xh, __half* __restrict__ wh)
{
    const int b = blockIdx.x;
    const float* src;
    __half* dst;
    int lb;
    if (b < 4096) { src = x; dst = xh; lb = b; }
    else {
        const int r = b - 4096;
        const int w = r >> 10;
        src = (w == 0) ? w0 : (w == 1) ? w1 : (w == 2) ? w2 : w3;
        dst = wh + (size_t)w * D_MODEL * D_MODEL;
        lb = r & 1023;
    }
    const size_t i = ((size_t)lb * 256 + threadIdx.x) * 4;
    float4 v = *(const float4*)(src + i);
    *(uint2*)(dst + i) = make_uint2(pk_h2(v.x, v.y), pk_h2(v.z, v.w));
}

/* ============================================================
 * fp16 single-pass GEMM core, BK=64, fused-QKV aware.
 * CTA 128x128, 8 warps (2x4), warp tile 64x32, mma.m16n8k16.
 * cp.async double-buffered.
 * ============================================================ */
#define SPITCH 144             /* 64 halves (128B) + 16B pad */
#define TBYTES (128 * SPITCH)  /* 18432 */
#define GSTG (2 * TBYTES)      /* 36864 */
#define GEMM_SMEM (2 * GSTG)   /* 73728 */

__device__ __forceinline__ void
gemm_core(const __half* __restrict__ A, const __half* __restrict__ B,
          float* __restrict__ C, int m0, int n0, int K, int N, char* smem)
{
    const uint32_t su = smem_to_u32(smem);
    const int tid    = threadIdx.x;
    const int lane   = tid & 31;
    const int wid    = tid >> 5;
    const int warp_m = wid >> 2;
    const int warp_n = wid & 3;

    const int nchunks = K / 64;   /* 16 */

    auto issue_stage = [&](int s, int i) {
        const uint32_t sb = su + s * GSTG;
        #pragma unroll
        for (int t = 0; t < 4; t++) {
            const int idx = tid + t * 256;          /* 0..1023 */
            const int row = idx >> 3, c = idx & 7;
            const uint32_t so = (uint32_t)row * SPITCH + c * 16;
            const size_t ga = (size_t)(m0 + row) * K + i * 64 + c * 8;
            const size_t gb = (size_t)(n0 + row) * K + i * 64 + c * 8;
            CP_ASYNC16(sb + so, A + ga);
            CP_ASYNC16(sb + TBYTES + so, B + gb);
        }
        CP_COMMIT();
    };

    issue_stage(0, 0);

    const uint32_t a_ld = su + (uint32_t)(warp_m * 64 + (lane & 15)) * SPITCH + (lane >> 4) * 16;
    const uint32_t b_ld = su + TBYTES + (uint32_t)(warp_n * 32 + (lane & 15)) * SPITCH + (lane >> 4) * 16;

    float acc[4][4][4] = {};

    for (int i = 0; i < nchunks; i++) {
        const int s = i & 1;
        if (i + 1 < nchunks) { issue_stage(s ^ 1, i + 1); CP_WAIT1(); }
        else                 { CP_WAIT0(); }
        __syncthreads();

        const uint32_t stb = s * GSTG;
        #pragma unroll
        for (int ks = 0; ks < 4; ks++) {
            uint32_t af[4][4];
            #pragma unroll
            for (int mt = 0; mt < 4; mt++)
                LDSM_X4(af[mt][0], af[mt][1], af[mt][2], af[mt][3],
                        a_ld + stb + mt * 16 * SPITCH + ks * 32);
            uint32_t bf[4][2];
            #pragma unroll
            for (int nb = 0; nb < 2; nb++) {
                uint32_t r0, r1, r2, r3;
                LDSM_X4(r0, r1, r2, r3, b_ld + stb + nb * 16 * SPITCH + ks * 32);
                bf[nb * 2][0]     = r0; bf[nb * 2][1]     = r2;
                bf[nb * 2 + 1][0] = r1; bf[nb * 2 + 1][1] = r3;
            }
            #pragma unroll
            for (int mt = 0; mt < 4; mt++)
                #pragma unroll
                for (int nt = 0; nt < 4; nt++)
                    MMA_FP16(acc[mt][nt], af[mt], bf[nt]);
        }
        __syncthreads();
    }

    #pragma unroll
    for (int mt = 0; mt < 4; mt++) {
        const int m = m0 + warp_m * 64 + mt * 16 + (lane >> 2);
        #pragma unroll
        for (int nt = 0; nt < 4; nt++) {
            const int n = n0 + warp_n * 32 + nt * 8 + (lane & 3) * 2;
            *(float2*)(C + (size_t)m * N + n) =
                make_float2(acc[mt][nt][0], acc[mt][nt][1]);
            *(float2*)(C + (size_t)(m + 8) * N + n) =
                make_float2(acc[mt][nt][2], acc[mt][nt][3]);
        }
    }
}

/* fused QKV: grid (24, 32); blockIdx.x selects weight & n-tile */
__global__ void __launch_bounds__(256, 2)
gemm_qkv_kernel(const __half* __restrict__ xh, const __half* __restrict__ wh,
                float* __restrict__ q, float* __restrict__ k, float* __restrict__ v)
{
    extern __shared__ __align__(16) char smem[];
    const int w  = blockIdx.x >> 3;          /* 0..2 */
    const int n0 = (blockIdx.x & 7) * 128;
    const int m0 = blockIdx.y * 128;
    const __half* B = wh + (size_t)w * D_MODEL * D_MODEL;
    float* C = (w == 0) ? q : (w == 1) ? k : v;
    gemm_core(xh, B, C, m0, n0, D_MODEL, D_MODEL, smem);
}

/* single GEMM (output projection) */
__global__ void __launch_bounds__(256, 2)
gemm_fp16_kernel(const __half* __restrict__ A, const __half* __restrict__ B,
                 float* __restrict__ C)
{
    extern __shared__ __align__(16) char smem[];
    gemm_core(A, B, C, blockIdx.y * 128, blockIdx.x * 128, D_MODEL, D_MODEL, smem);
}

/* ============================================================
 * Fused RoPE for Q and K -> fp16 (scale folded into Q).
 * ============================================================ */
__global__ void __launch_bounds__(256)
rope2_kernel(const float* __restrict__ q, const float* __restrict__ k,
             __half* __restrict__ qh, __half* __restrict__ kh)
{
    __shared__ float invf[32];
    const int tid = threadIdx.x;
    if (tid < 32) invf[tid] = (float)pow(10000.0, -(double)tid / 32.0);
    __syncthreads();

    const int bs   = blockIdx.x * 8 + (tid >> 5);
    const int lane = tid & 31;
    const int pos  = bs & (SEQ - 1);

    float s1, c1, s2, c2;
    sincosf((float)pos * invf[(2 * lane) & 31],     &s1, &c1);
    sincosf((float)pos * invf[(2 * lane + 1) & 31], &s2, &c2);

    const size_t base = (size_t)bs * D_MODEL;
    #pragma unroll
    for (int h = 0; h < N_HEADS; h++) {
        const size_t ro = base + h * 64;
        {
            float x0 = q[ro + 2 * lane], x1 = q[ro + 2 * lane + 1];
            qh[ro + lane]      = __float2half_rn((x0 * c1 - x1 * s1) * 0.125f);
            qh[ro + 32 + lane] = __float2half_rn((x0 * s2 + x1 * c2) * 0.125f);
        }
        {
            float x0 = k[ro + 2 * lane], x1 = k[ro + 2 * lane + 1];
            kh[ro + lane]      = __float2half_rn(x0 * c1 - x1 * s1);
            kh[ro + 32 + lane] = __float2half_rn(x0 * s2 + x1 * c2);
        }
    }
}

/* ============================================================
 * V transpose -> vt [bh][d][S] fp16.
 * ============================================================ */
__global__ void __launch_bounds__(256)
vtrans_kernel(const float* __restrict__ v, __half* __restrict__ vt)
{
    __shared__ float t[64][65];
    const int sblk = blockIdx.x;
    const int bh   = blockIdx.y;
    const int tid  = threadIdx.x;

    {
        const int row = tid >> 2;
        const int c0  = (tid & 3) * 16;
        const size_t gaddr = ((size_t)(bh >> 4) * SEQ + sblk * 64 + row) * D_MODEL
                           + (bh & 15) * 64 + c0;
        #pragma unroll
        for (int f = 0; f < 4; f++) {
            float4 vv = *(const float4*)(v + gaddr + f * 4);
            t[row][c0 + f * 4 + 0] = vv.x; t[row][c0 + f * 4 + 1] = vv.y;
            t[row][c0 + f * 4 + 2] = vv.z; t[row][c0 + f * 4 + 3] = vv.w;
        }
    }
    __syncthreads();

    const int d  = tid >> 2;
    const int k0 = (tid & 3) * 16;
    uint32_t out[8];
    #pragma unroll
    for (int p = 0; p < 8; p++)
        out[p] = pk_h2(t[k0 + 2 * p][d], t[k0 + 2 * p + 1][d]);
    const size_t dst = ((size_t)bh * 64 + d) * SEQ + sblk * 64 + k0;
    *(uint4*)(vt + dst)     = *(uint4*)(out);
    *(uint4*)(vt + dst + 8) = *(uint4*)(out + 4);
}

/* ============================================================
 * Flash attention, causal, single-pass fp16 mma (unchanged).
 * ============================================================ */
#define AQP 144
#define AQT (128 * AQP)
#define AKT (64 * AQP)
#define ASTG (2 * AKT)
#define ATTN_SMEM (AQT + 2 * ASTG)   /* 55296 */
#define NQB (SEQ / 128)

__global__ void __launch_bounds__(256, 2)
attn_mma_kernel(const __half* __restrict__ qh, const __half* __restrict__ kh,
                const __half* __restrict__ vt, __half* __restrict__ o)
{
    extern __shared__ __align__(16) char sm[];
    const uint32_t su = smem_to_u32(sm);

    const int bh   = blockIdx.y;
    const int tid  = threadIdx.x;
    const int lane = tid & 31;
    const int wid  = tid >> 5;

    const int b = bh >> 4, h = bh & 15;
    const size_t qkrow0 = ((size_t)b * SEQ) * D_MODEL + (size_t)h * 64;
    const size_t vtrow0 = ((size_t)bh * 64) * SEQ;

    const uint32_t a_ld = su + (uint32_t)(wid * 16 + (lane & 15)) * AQP + (lane >> 4) * 16;
    const uint32_t t_ld = su + AQT + (uint32_t)(lane & 15) * AQP + (lane >> 4) * 16;

    auto issue_stage = [&](int s, int kb) {
        const uint32_t sb = su + AQT + s * ASTG;
        #pragma unroll
        for (int i = 0; i < 2; i++) {
            const int idx = tid + i * 256;
            const int row = idx >> 3, c = idx & 7;
            const uint32_t so = (uint32_t)row * AQP + c * 16;
            const size_t gk = qkrow0 + (size_t)(kb * 64 + row) * D_MODEL + c * 8;
            const size_t gv = vtrow0 + (size_t)row * SEQ + kb * 64 + c * 8;
            CP_ASYNC16(sb + so, kh + gk);
            CP_ASYNC16(sb + AKT + so, vt + gv);
        }
        CP_COMMIT();
    };

    #pragma unroll 1
    for (int qi = 0; qi < 2; qi++) {
        const int qb = (qi == 0) ? blockIdx.x : (NQB - 1 - blockIdx.x);

        {
            #pragma unroll
            for (int i = 0; i < 4; i++) {
                const int idx = tid + i * 256;
                const int row = idx >> 3, c = idx & 7;
                const size_t g = qkrow0 + (size_t)(qb * 128 + row) * D_MODEL + c * 8;
                *(uint4*)(sm + (size_t)row * AQP + c * 16) = *(const uint4*)(qh + g);
            }
        }

        const int nkb = 2 * qb + 2;
        issue_stage(0, 0);

        float acc[8][4] = {};
        float mo1 = -1e30f, mo2 = -1e30f, l1 = 0.0f, l2 = 0.0f;
        const int q1g = qb * 128 + wid * 16 + (lane >> 2);
        const int warp_qmax = qb * 128 + wid * 16 + 15;

        for (int kb = 0; kb < nkb; kb++) {
            const int s = kb & 1;
            if (kb + 1 < nkb) { issue_stage(s ^ 1, kb + 1); CP_WAIT1(); }
            else              { CP_WAIT0(); }
            __syncthreads();

            const bool tile_active = (kb * 64 <= warp_qmax);

            if (tile_active) {
                const uint32_t k_ld = t_ld + s * ASTG;
                const uint32_t v_ld = k_ld + AKT;

                float sc[8][4] = {};
                #pragma unroll
                for (int ks = 0; ks < 4; ks++) {
                    uint32_t af[4];
                    LDSM_X4(af[0], af[1], af[2], af[3], a_ld + ks * 32);
                    #pragma unroll
                    for (int nb = 0; nb < 4; nb++) {
                        if (kb * 64 + nb * 16 > warp_qmax) continue;
                        uint32_t r0, r1, r2, r3;
                        LDSM_X4(r0, r1, r2, r3, k_ld + nb * 16 * AQP + ks * 32);
                        uint32_t be[2] = {r0, r2}, bo[2] = {r1, r3};
                        MMA_FP16(sc[2 * nb],     af, be);
                        MMA_FP16(sc[2 * nb + 1], af, bo);
                    }
                }

                if (kb * 64 + 63 > qb * 128 + wid * 16) {
                    #pragma unroll
                    for (int j = 0; j < 8; j++) {
                        const int c = kb * 64 + j * 8 + (lane & 3) * 2;
                        if (c     > q1g)     sc[j][0] = -1e30f;
                        if (c + 1 > q1g)     sc[j][1] = -1e30f;
                        if (c     > q1g + 8) sc[j][2] = -1e30f;
                        if (c + 1 > q1g + 8) sc[j][3] = -1e30f;
                    }
                }

                float m1 = -1e30f, m2 = -1e30f;
                #pragma unroll
                for (int j = 0; j < 8; j++) {
                    m1 = fmaxf(m1, fmaxf(sc[j][0], sc[j][1]));
                    m2 = fmaxf(m2, fmaxf(sc[j][2], sc[j][3]));
                }
                m1 = fmaxf(m1, __shfl_xor_sync(0xffffffffu, m1, 1));
                m1 = fmaxf(m1, __shfl_xor_sync(0xffffffffu, m1, 2));
                m2 = fmaxf(m2, __shfl_xor_sync(0xffffffffu, m2, 1));
                m2 = fmaxf(m2, __shfl_xor_sync(0xffffffffu, m2, 2));
                const float mn1 = fmaxf(mo1, m1), mn2 = fmaxf(mo2, m2);
                const float sc1 = __expf(mo1 - mn1), sc2 = __expf(mo2 - mn2);
                float sum1 = 0.0f, sum2 = 0.0f;
                #pragma unroll
                for (int j = 0; j < 8; j++) {
                    sc[j][0] = __expf(sc[j][0] - mn1); sum1 += sc[j][0];
                    sc[j][1] = __expf(sc[j][1] - mn1); sum1 += sc[j][1];
                    sc[j][2] = __expf(sc[j][2] - mn2); sum2 += sc[j][2];
                    sc[j][3] = __expf(sc[j][3] - mn2); sum2 += sc[j][3];
                }
                sum1 += __shfl_xor_sync(0xffffffffu, sum1, 1);
                sum1 += __shfl_xor_sync(0xffffffffu, sum1, 2);
                sum2 += __shfl_xor_sync(0xffffffffu, sum2, 1);
                sum2 += __shfl_xor_sync(0xffffffffu, sum2, 2);
                l1 = l1 * sc1 + sum1; l2 = l2 * sc2 + sum2;
                mo1 = mn1; mo2 = mn2;
                #pragma unroll
                for (int j = 0; j < 8; j++) {
                    acc[j][0] *= sc1; acc[j][1] *= sc1;
                    acc[j][2] *= sc2; acc[j][3] *= sc2;
                }

                #pragma unroll
                for (int kt = 0; kt < 4; kt++) {
                    if (kb * 64 + kt * 16 > warp_qmax) continue;
                    uint32_t pa[4];
                    pa[0] = pk_h2(sc[2 * kt][0],     sc[2 * kt][1]);
                    pa[1] = pk_h2(sc[2 * kt][2],     sc[2 * kt][3]);
                    pa[2] = pk_h2(sc[2 * kt + 1][0], sc[2 * kt + 1][1]);
                    pa[3] = pk_h2(sc[2 * kt + 1][2], sc[2 * kt + 1][3]);
                    #pragma unroll
                    for (int nb = 0; nb < 4; nb++) {
                        uint32_t r0, r1, r2, r3;
                        LDSM_X4(r0, r1, r2, r3, v_ld + nb * 16 * AQP + kt * 32);
                        uint32_t be[2] = {r0, r2}, bo[2] = {r1, r3};
                        MMA_FP16(acc[2 * nb],     pa, be);
                        MMA_FP16(acc[2 * nb + 1], pa, bo);
                    }
                }
            }
            __syncthreads();
        }

        const float i1 = 1.0f / l1, i2 = 1.0f / l2;
        const size_t r1a = qkrow0 + (size_t)(qb * 128 + wid * 16 + (lane >> 2)) * D_MODEL;
        const size_t r2a = r1a + 8 * D_MODEL;
        #pragma unroll
        for (int j = 0; j < 8; j++) {
            const int c = j * 8 + (lane & 3) * 2;
            *(uint32_t*)(o + r1a + c) = pk_h2(acc[j][0] * i1, acc[j][1] * i1);
            *(uint32_t*)(o + r2a + c) = pk_h2(acc[j][2] * i2, acc[j][3] * i2);
        }
        __syncthreads();
    }
}

/* ============================================================ */
extern "C" void kernel_launch(void* const* d_in, const int* in_sizes, int n_in,
                              void* d_out, int out_size)
{
    const float* x  = (const float*)d_in[0];
    const float* W[4] = { (const float*)d_in[1], (const float*)d_in[2],
                          (const float*)d_in[3], (const float*)d_in[4] };
    float* out = (float*)d_out;

    float *qp, *kp, *vp;
    __half *xh, *wh, *qhp, *khp, *vtp, *aop;
    cudaGetSymbolAddress((void**)&qp, g_q);
    cudaGetSymbolAddress((void**)&kp, g_k);
    cudaGetSymbolAddress((void**)&vp, g_v);
    cudaGetSymbolAddress((void**)&xh, g_xh);
    cudaGetSymbolAddress((void**)&wh, g_wh);
    cudaGetSymbolAddress((void**)&qhp, g_qh);
    cudaGetSymbolAddress((void**)&khp, g_kh);
    cudaGetSymbolAddress((void**)&vtp, g_vt);
    cudaGetSymbolAddress((void**)&aop, g_ao);

    static bool attr_done = false;
    if (!attr_done) {
        cudaFuncSetAttribute(gemm_qkv_kernel,
                             cudaFuncAttributeMaxDynamicSharedMemorySize, GEMM_SMEM);
        cudaFuncSetAttribute(gemm_fp16_kernel,
                             cudaFuncAttributeMaxDynamicSharedMemorySize, GEMM_SMEM);
        cudaFuncSetAttribute(attn_mma_kernel,
                             cudaFuncAttributeMaxDynamicSharedMemorySize, ATTN_SMEM);
        attr_done = true;
    }

    const size_t WSZ = (size_t)D_MODEL * D_MODEL;

    convert_all_kernel<<<8192, 256>>>(x, W[0], W[1], W[2], W[3], xh, wh);

    /* fused QKV: grid (24, 32) */
    gemm_qkv_kernel<<<dim3(24, M_TOT / 128), 256, GEMM_SMEM>>>(xh, wh, qp, kp, vp);

    rope2_kernel<<<M_TOT / 8, 256>>>(qp, kp, qhp, khp);
    vtrans_kernel<<<dim3(SEQ / 64, BATCH * N_HEADS), 256>>>(vp, vtp);

    attn_mma_kernel<<<dim3(NQB / 2, BATCH * N_HEADS), 256, ATTN_SMEM>>>(
        qhp, khp, vtp, aop);

    gemm_fp16_kernel<<<dim3(8, M_TOT / 128), 256, GEMM_SMEM>>>(aop, wh + 3 * WSZ, out);
}

// round 16
// speedup vs baseline: 2.1385x; 1.0338x over previous
#include <cuda_runtime.h>
#include <cuda_fp16.h>
#include <math.h>
#include <stdint.h>

#define D_MODEL 1024
#define N_HEADS 16
#define HEAD_DIM 64
#define BATCH 2
#define SEQ 2048
#define M_TOT (BATCH * SEQ)   /* 4096 */

/* ---- scratch (allocation-free: __device__ globals) ---- */
__device__ __half g_xh[(size_t)M_TOT * D_MODEL];
__device__ __half g_wh[4][(size_t)D_MODEL * D_MODEL];
__device__ __half g_qp[(size_t)M_TOT * D_MODEL];   /* q proj (pre-rope) */
__device__ __half g_kp[(size_t)M_TOT * D_MODEL];   /* k proj (pre-rope) */
__device__ __half g_vp[(size_t)M_TOT * D_MODEL];   /* v proj */
__device__ __half g_qh[(size_t)M_TOT * D_MODEL];   /* rope'd q */
__device__ __half g_kh[(size_t)M_TOT * D_MODEL];   /* rope'd k */
__device__ __half g_vt[(size_t)M_TOT * D_MODEL];   /* V^T [bh][d][S] */
__device__ __half g_ao[(size_t)M_TOT * D_MODEL];   /* attn out */

__device__ __forceinline__ uint32_t smem_to_u32(const void* p) {
    uint32_t a;
    asm("{ .reg .u64 t; cvta.to.shared.u64 t, %1; cvt.u32.u64 %0, t; }" : "=r"(a) : "l"(p));
    return a;
}

#define LDSM_X4(r0, r1, r2, r3, addr) \
    asm volatile("ldmatrix.sync.aligned.m8n8.x4.shared.b16 {%0,%1,%2,%3}, [%4];" \
                 : "=r"(r0), "=r"(r1), "=r"(r2), "=r"(r3) : "r"(addr))

#define MMA_FP16(c, a, b) \
    asm volatile("mma.sync.aligned.m16n8k16.row.col.f32.f16.f16.f32 " \
                 "{%0,%1,%2,%3},{%4,%5,%6,%7},{%8,%9},{%0,%1,%2,%3};" \
                 : "+f"((c)[0]), "+f"((c)[1]), "+f"((c)[2]), "+f"((c)[3]) \
                 : "r"((a)[0]), "r"((a)[1]), "r"((a)[2]), "r"((a)[3]), \
                   "r"((b)[0]), "r"((b)[1]))

#define CP_ASYNC16(saddr, gptr) \
    asm volatile("cp.async.cg.shared.global [%0], [%1], 16;" \
                 :: "r"(saddr), "l"(gptr) : "memory")
#define CP_COMMIT() asm volatile("cp.async.commit_group;" ::: "memory")
#define CP_WAIT0()  asm volatile("cp.async.wait_group 0;" ::: "memory")
#define CP_WAIT1()  asm volatile("cp.async.wait_group 1;" ::: "memory")

__device__ __forceinline__ uint32_t pk_h2(float a, float b) {
    __half2 h = __floats2half2_rn(a, b);
    return *(uint32_t*)&h;
}

/* ============================================================
 * Merged fp32 -> fp16 conversion for x + all 4 weights.
 * ============================================================ */
__global__ void __launch_bounds__(256)
convert_all_kernel(const float* __restrict__ x,
                   const float* __restrict__ w0, const float* __restrict__ w1,
                   const float* __restrict__ w2, const float* __restrict__ w3,
                   __half* __restrict__ xh, __half* __restrict__ wh)
{
    const int b = blockIdx.x;
    const float* src;
    __half* dst;
    int lb;
    if (b < 4096) { src = x; dst = xh; lb = b; }
    else {
        const int r = b - 4096;
        const int w = r >> 10;
        src = (w == 0) ? w0 : (w == 1) ? w1 : (w == 2) ? w2 : w3;
        dst = wh + (size_t)w * D_MODEL * D_MODEL;
        lb = r & 1023;
    }
    const size_t i = ((size_t)lb * 256 + threadIdx.x) * 4;
    float4 v = *(const float4*)(src + i);
    *(uint2*)(dst + i) = make_uint2(pk_h2(v.x, v.y), pk_h2(v.z, v.w));
}

/* ============================================================
 * fp16 single-pass GEMM core, BK=64, fp16 or fp32 output.
 * CTA 128x128, 8 warps (2x4), warp tile 64x32, mma.m16n8k16.
 * ============================================================ */
#define SPITCH 144
#define TBYTES (128 * SPITCH)  /* 18432 */
#define GSTG (2 * TBYTES)      /* 36864 */
#define GEMM_SMEM (2 * GSTG)   /* 73728 */

template <typename OutT>
__device__ __forceinline__ void
gemm_core(const __half* __restrict__ A, const __half* __restrict__ B,
          OutT* __restrict__ C, int m0, int n0, int K, int N, char* smem)
{
    const uint32_t su = smem_to_u32(smem);
    const int tid    = threadIdx.x;
    const int lane   = tid & 31;
    const int wid    = tid >> 5;
    const int warp_m = wid >> 2;
    const int warp_n = wid & 3;

    const int nchunks = K / 64;   /* 16 */

    auto issue_stage = [&](int s, int i) {
        const uint32_t sb = su + s * GSTG;
        #pragma unroll
        for (int t = 0; t < 4; t++) {
            const int idx = tid + t * 256;
            const int row = idx >> 3, c = idx & 7;
            const uint32_t so = (uint32_t)row * SPITCH + c * 16;
            const size_t ga = (size_t)(m0 + row) * K + i * 64 + c * 8;
            const size_t gb = (size_t)(n0 + row) * K + i * 64 + c * 8;
            CP_ASYNC16(sb + so, A + ga);
            CP_ASYNC16(sb + TBYTES + so, B + gb);
        }
        CP_COMMIT();
    };

    issue_stage(0, 0);

    const uint32_t a_ld = su + (uint32_t)(warp_m * 64 + (lane & 15)) * SPITCH + (lane >> 4) * 16;
    const uint32_t b_ld = su + TBYTES + (uint32_t)(warp_n * 32 + (lane & 15)) * SPITCH + (lane >> 4) * 16;

    float acc[4][4][4] = {};

    for (int i = 0; i < nchunks; i++) {
        const int s = i & 1;
        if (i + 1 < nchunks) { issue_stage(s ^ 1, i + 1); CP_WAIT1(); }
        else                 { CP_WAIT0(); }
        __syncthreads();

        const uint32_t stb = s * GSTG;
        #pragma unroll
        for (int ks = 0; ks < 4; ks++) {
            uint32_t af[4][4];
            #pragma unroll
            for (int mt = 0; mt < 4; mt++)
                LDSM_X4(af[mt][0], af[mt][1], af[mt][2], af[mt][3],
                        a_ld + stb + mt * 16 * SPITCH + ks * 32);
            uint32_t bf[4][2];
            #pragma unroll
            for (int nb = 0; nb < 2; nb++) {
                uint32_t r0, r1, r2, r3;
                LDSM_X4(r0, r1, r2, r3, b_ld + stb + nb * 16 * SPITCH + ks * 32);
                bf[nb * 2][0]     = r0; bf[nb * 2][1]     = r2;
                bf[nb * 2 + 1][0] = r1; bf[nb * 2 + 1][1] = r3;
            }
            #pragma unroll
            for (int mt = 0; mt < 4; mt++)
                #pragma unroll
                for (int nt = 0; nt < 4; nt++)
                    MMA_FP16(acc[mt][nt], af[mt], bf[nt]);
        }
        __syncthreads();
    }

    #pragma unroll
    for (int mt = 0; mt < 4; mt++) {
        const int m = m0 + warp_m * 64 + mt * 16 + (lane >> 2);
        #pragma unroll
        for (int nt = 0; nt < 4; nt++) {
            const int n = n0 + warp_n * 32 + nt * 8 + (lane & 3) * 2;
            if constexpr (sizeof(OutT) == 2) {
                *(uint32_t*)((__half*)C + (size_t)m * N + n) =
                    pk_h2(acc[mt][nt][0], acc[mt][nt][1]);
                *(uint32_t*)((__half*)C + (size_t)(m + 8) * N + n) =
                    pk_h2(acc[mt][nt][2], acc[mt][nt][3]);
            } else {
                *(float2*)((float*)C + (size_t)m * N + n) =
                    make_float2(acc[mt][nt][0], acc[mt][nt][1]);
                *(float2*)((float*)C + (size_t)(m + 8) * N + n) =
                    make_float2(acc[mt][nt][2], acc[mt][nt][3]);
            }
        }
    }
}

/* fused QKV: grid (24, 32); fp16 output */
__global__ void __launch_bounds__(256, 2)
gemm_qkv_kernel(const __half* __restrict__ xh, const __half* __restrict__ wh,
                __half* __restrict__ q, __half* __restrict__ k, __half* __restrict__ v)
{
    extern __shared__ __align__(16) char smem[];
    const int w  = blockIdx.x >> 3;
    const int n0 = (blockIdx.x & 7) * 128;
    const int m0 = blockIdx.y * 128;
    const __half* B = wh + (size_t)w * D_MODEL * D_MODEL;
    __half* C = (w == 0) ? q : (w == 1) ? k : v;
    gemm_core<__half>(xh, B, C, m0, n0, D_MODEL, D_MODEL, smem);
}

/* output projection: fp32 output */
__global__ void __launch_bounds__(256, 2)
gemm_fp16_kernel(const __half* __restrict__ A, const __half* __restrict__ B,
                 float* __restrict__ C)
{
    extern __shared__ __align__(16) char smem[];
    gemm_core<float>(A, B, C, blockIdx.y * 128, blockIdx.x * 128, D_MODEL, D_MODEL, smem);
}

/* ============================================================
 * Fused RoPE (blocks 0..511) + V-transpose (blocks 512..1535).
 * All fp16 in/out.
 * ============================================================ */
__global__ void __launch_bounds__(256)
rope_vtrans_kernel(const __half* __restrict__ qp, const __half* __restrict__ kp,
                   const __half* __restrict__ vp,
                   __half* __restrict__ qh, __half* __restrict__ kh,
                   __half* __restrict__ vt)
{
    __shared__ float t[64][65];
    const int tid = threadIdx.x;

    if (blockIdx.x < 512) {
        /* ---- RoPE ---- */
        __shared__ float invf[32];
        if (tid < 32) invf[tid] = (float)pow(10000.0, -(double)tid / 32.0);
        __syncthreads();

        const int bs   = blockIdx.x * 8 + (tid >> 5);
        const int lane = tid & 31;
        const int pos  = bs & (SEQ - 1);

        float s1, c1, s2, c2;
        sincosf((float)pos * invf[(2 * lane) & 31],     &s1, &c1);
        sincosf((float)pos * invf[(2 * lane + 1) & 31], &s2, &c2);

        const size_t base = (size_t)bs * D_MODEL;
        #pragma unroll
        for (int h = 0; h < N_HEADS; h++) {
            const size_t ro = base + h * 64;
            {
                __half2 xv = *(const __half2*)(qp + ro + 2 * lane);
                float x0 = __low2float(xv), x1 = __high2float(xv);
                qh[ro + lane]      = __float2half_rn((x0 * c1 - x1 * s1) * 0.125f);
                qh[ro + 32 + lane] = __float2half_rn((x0 * s2 + x1 * c2) * 0.125f);
            }
            {
                __half2 xv = *(const __half2*)(kp + ro + 2 * lane);
                float x0 = __low2float(xv), x1 = __high2float(xv);
                kh[ro + lane]      = __float2half_rn(x0 * c1 - x1 * s1);
                kh[ro + 32 + lane] = __float2half_rn(x0 * s2 + x1 * c2);
            }
        }
    } else {
        /* ---- V transpose: r = 0..1023 -> (sblk, bh) ---- */
        const int r    = blockIdx.x - 512;
        const int sblk = r & 31;
        const int bh   = r >> 5;

        {
            const int row = tid >> 2;
            const int c0  = (tid & 3) * 16;
            const size_t gaddr = ((size_t)(bh >> 4) * SEQ + sblk * 64 + row) * D_MODEL
                               + (bh & 15) * 64 + c0;
            #pragma unroll
            for (int f = 0; f < 2; f++) {
                uint4 pk = *(const uint4*)(vp + gaddr + f * 8);
                const __half* hp = (const __half*)&pk;
                #pragma unroll
                for (int e = 0; e < 8; e++)
                    t[row][c0 + f * 8 + e] = __half2float(hp[e]);
            }
        }
        __syncthreads();

        const int d  = tid >> 2;
        const int k0 = (tid & 3) * 16;
        uint32_t out[8];
        #pragma unroll
        for (int p = 0; p < 8; p++)
            out[p] = pk_h2(t[k0 + 2 * p][d], t[k0 + 2 * p + 1][d]);
        const size_t dst = ((size_t)bh * 64 + d) * SEQ + sblk * 64 + k0;
        *(uint4*)(vt + dst)     = *(uint4*)(out);
        *(uint4*)(vt + dst + 8) = *(uint4*)(out + 4);
    }
}

/* ============================================================
 * Flash attention, causal, single-pass fp16 mma (unchanged).
 * ============================================================ */
#define AQP 144
#define AQT (128 * AQP)
#define AKT (64 * AQP)
#define ASTG (2 * AKT)
#define ATTN_SMEM (AQT + 2 * ASTG)   /* 55296 */
#define NQB (SEQ / 128)

__global__ void __launch_bounds__(256, 2)
attn_mma_kernel(const __half* __restrict__ qh, const __half* __restrict__ kh,
                const __half* __restrict__ vt, __half* __restrict__ o)
{
    extern __shared__ __align__(16) char sm[];
    const uint32_t su = smem_to_u32(sm);

    const int bh   = blockIdx.y;
    const int tid  = threadIdx.x;
    const int lane = tid & 31;
    const int wid  = tid >> 5;

    const int b = bh >> 4, h = bh & 15;
    const size_t qkrow0 = ((size_t)b * SEQ) * D_MODEL + (size_t)h * 64;
    const size_t vtrow0 = ((size_t)bh * 64) * SEQ;

    const uint32_t a_ld = su + (uint32_t)(wid * 16 + (lane & 15)) * AQP + (lane >> 4) * 16;
    const uint32_t t_ld = su + AQT + (uint32_t)(lane & 15) * AQP + (lane >> 4) * 16;

    auto issue_stage = [&](int s, int kb) {
        const uint32_t sb = su + AQT + s * ASTG;
        #pragma unroll
        for (int i = 0; i < 2; i++) {
            const int idx = tid + i * 256;
            const int row = idx >> 3, c = idx & 7;
            const uint32_t so = (uint32_t)row * AQP + c * 16;
            const size_t gk = qkrow0 + (size_t)(kb * 64 + row) * D_MODEL + c * 8;
            const size_t gv = vtrow0 + (size_t)row * SEQ + kb * 64 + c * 8;
            CP_ASYNC16(sb + so, kh + gk);
            CP_ASYNC16(sb + AKT + so, vt + gv);
        }
        CP_COMMIT();
    };

    #pragma unroll 1
    for (int qi = 0; qi < 2; qi++) {
        const int qb = (qi == 0) ? blockIdx.x : (NQB - 1 - blockIdx.x);

        {
            #pragma unroll
            for (int i = 0; i < 4; i++) {
                const int idx = tid + i * 256;
                const int row = idx >> 3, c = idx & 7;
                const size_t g = qkrow0 + (size_t)(qb * 128 + row) * D_MODEL + c * 8;
                *(uint4*)(sm + (size_t)row * AQP + c * 16) = *(const uint4*)(qh + g);
            }
        }

        const int nkb = 2 * qb + 2;
        issue_stage(0, 0);

        float acc[8][4] = {};
        float mo1 = -1e30f, mo2 = -1e30f, l1 = 0.0f, l2 = 0.0f;
        const int q1g = qb * 128 + wid * 16 + (lane >> 2);
        const int warp_qmax = qb * 128 + wid * 16 + 15;

        for (int kb = 0; kb < nkb; kb++) {
            const int s = kb & 1;
            if (kb + 1 < nkb) { issue_stage(s ^ 1, kb + 1); CP_WAIT1(); }
            else              { CP_WAIT0(); }
            __syncthreads();

            const bool tile_active = (kb * 64 <= warp_qmax);

            if (tile_active) {
                const uint32_t k_ld = t_ld + s * ASTG;
                const uint32_t v_ld = k_ld + AKT;

                float sc[8][4] = {};
                #pragma unroll
                for (int ks = 0; ks < 4; ks++) {
                    uint32_t af[4];
                    LDSM_X4(af[0], af[1], af[2], af[3], a_ld + ks * 32);
                    #pragma unroll
                    for (int nb = 0; nb < 4; nb++) {
                        if (kb * 64 + nb * 16 > warp_qmax) continue;
                        uint32_t r0, r1, r2, r3;
                        LDSM_X4(r0, r1, r2, r3, k_ld + nb * 16 * AQP + ks * 32);
                        uint32_t be[2] = {r0, r2}, bo[2] = {r1, r3};
                        MMA_FP16(sc[2 * nb],     af, be);
                        MMA_FP16(sc[2 * nb + 1], af, bo);
                    }
                }

                if (kb * 64 + 63 > qb * 128 + wid * 16) {
                    #pragma unroll
                    for (int j = 0; j < 8; j++) {
                        const int c = kb * 64 + j * 8 + (lane & 3) * 2;
                        if (c     > q1g)     sc[j][0] = -1e30f;
                        if (c + 1 > q1g)     sc[j][1] = -1e30f;
                        if (c     > q1g + 8) sc[j][2] = -1e30f;
                        if (c + 1 > q1g + 8) sc[j][3] = -1e30f;
                    }
                }

                float m1 = -1e30f, m2 = -1e30f;
                #pragma unroll
                for (int j = 0; j < 8; j++) {
                    m1 = fmaxf(m1, fmaxf(sc[j][0], sc[j][1]));
                    m2 = fmaxf(m2, fmaxf(sc[j][2], sc[j][3]));
                }
                m1 = fmaxf(m1, __shfl_xor_sync(0xffffffffu, m1, 1));
                m1 = fmaxf(m1, __shfl_xor_sync(0xffffffffu, m1, 2));
                m2 = fmaxf(m2, __shfl_xor_sync(0xffffffffu, m2, 1));
                m2 = fmaxf(m2, __shfl_xor_sync(0xffffffffu, m2, 2));
                const float mn1 = fmaxf(mo1, m1), mn2 = fmaxf(mo2, m2);
                const float sc1 = __expf(mo1 - mn1), sc2 = __expf(mo2 - mn2);
                float sum1 = 0.0f, sum2 = 0.0f;
                #pragma unroll
                for (int j = 0; j < 8; j++) {
                    sc[j][0] = __expf(sc[j][0] - mn1); sum1 += sc[j][0];
                    sc[j][1] = __expf(sc[j][1] - mn1); sum1 += sc[j][1];
                    sc[j][2] = __expf(sc[j][2] - mn2); sum2 += sc[j][2];
                    sc[j][3] = __expf(sc[j][3] - mn2); sum2 += sc[j][3];
                }
                sum1 += __shfl_xor_sync(0xffffffffu, sum1, 1);
                sum1 += __shfl_xor_sync(0xffffffffu, sum1, 2);
                sum2 += __shfl_xor_sync(0xffffffffu, sum2, 1);
                sum2 += __shfl_xor_sync(0xffffffffu, sum2, 2);
                l1 = l1 * sc1 + sum1; l2 = l2 * sc2 + sum2;
                mo1 = mn1; mo2 = mn2;
                #pragma unroll
                for (int j = 0; j < 8; j++) {
                    acc[j][0] *= sc1; acc[j][1] *= sc1;
                    acc[j][2] *= sc2; acc[j][3] *= sc2;
                }

                #pragma unroll
                for (int kt = 0; kt < 4; kt++) {
                    if (kb * 64 + kt * 16 > warp_qmax) continue;
                    uint32_t pa[4];
                    pa[0] = pk_h2(sc[2 * kt][0],     sc[2 * kt][1]);
                    pa[1] = pk_h2(sc[2 * kt][2],     sc[2 * kt][3]);
                    pa[2] = pk_h2(sc[2 * kt + 1][0], sc[2 * kt + 1][1]);
                    pa[3] = pk_h2(sc[2 * kt + 1][2], sc[2 * kt + 1][3]);
                    #pragma unroll
                    for (int nb = 0; nb < 4; nb++) {
                        uint32_t r0, r1, r2, r3;
                        LDSM_X4(r0, r1, r2, r3, v_ld + nb * 16 * AQP + kt * 32);
                        uint32_t be[2] = {r0, r2}, bo[2] = {r1, r3};
                        MMA_FP16(acc[2 * nb],     pa, be);
                        MMA_FP16(acc[2 * nb + 1], pa, bo);
                    }
                }
            }
            __syncthreads();
        }

        const float i1 = 1.0f / l1, i2 = 1.0f / l2;
        const size_t r1a = qkrow0 + (size_t)(qb * 128 + wid * 16 + (lane >> 2)) * D_MODEL;
        const size_t r2a = r1a + 8 * D_MODEL;
        #pragma unroll
        for (int j = 0; j < 8; j++) {
            const int c = j * 8 + (lane & 3) * 2;
            *(uint32_t*)(o + r1a + c) = pk_h2(acc[j][0] * i1, acc[j][1] * i1);
            *(uint32_t*)(o + r2a + c) = pk_h2(acc[j][2] * i2, acc[j][3] * i2);
        }
        __syncthreads();
    }
}

/* ============================================================ */
extern "C" void kernel_launch(void* const* d_in, const int* in_sizes, int n_in,
                              void* d_out, int out_size)
{
    const float* x  = (const float*)d_in[0];
    const float* W[4] = { (const float*)d_in[1], (const float*)d_in[2],
                          (const float*)d_in[3], (const float*)d_in[4] };
    float* out = (float*)d_out;

    __half *xh, *wh, *qpp, *kpp, *vpp, *qhp, *khp, *vtp, *aop;
    cudaGetSymbolAddress((void**)&xh, g_xh);
    cudaGetSymbolAddress((void**)&wh, g_wh);
    cudaGetSymbolAddress((void**)&qpp, g_qp);
    cudaGetSymbolAddress((void**)&kpp, g_kp);
    cudaGetSymbolAddress((void**)&vpp, g_vp);
    cudaGetSymbolAddress((void**)&qhp, g_qh);
    cudaGetSymbolAddress((void**)&khp, g_kh);
    cudaGetSymbolAddress((void**)&vtp, g_vt);
    cudaGetSymbolAddress((void**)&aop, g_ao);

    static bool attr_done = false;
    if (!attr_done) {
        cudaFuncSetAttribute(gemm_qkv_kernel,
                             cudaFuncAttributeMaxDynamicSharedMemorySize, GEMM_SMEM);
        cudaFuncSetAttribute(gemm_fp16_kernel,
                             cudaFuncAttributeMaxDynamicSharedMemorySize, GEMM_SMEM);
        cudaFuncSetAttribute(attn_mma_kernel,
                             cudaFuncAttributeMaxDynamicSharedMemorySize, ATTN_SMEM);
        attr_done = true;
    }

    const size_t WSZ = (size_t)D_MODEL * D_MODEL;

    convert_all_kernel<<<8192, 256>>>(x, W[0], W[1], W[2], W[3], xh, wh);

    gemm_qkv_kernel<<<dim3(24, M_TOT / 128), 256, GEMM_SMEM>>>(xh, wh, qpp, kpp, vpp);

    rope_vtrans_kernel<<<1536, 256>>>(qpp, kpp, vpp, qhp, khp, vtp);

    attn_mma_kernel<<<dim3(NQB / 2, BATCH * N_HEADS), 256, ATTN_SMEM>>>(
        qhp, khp, vtp, aop);

    gemm_fp16_kernel<<<dim3(8, M_TOT / 128), 256, GEMM_SMEM>>>(aop, wh + 3 * WSZ, out);
}

// round 17
// speedup vs baseline: 2.1555x; 1.0079x over previous
#include <cuda_runtime.h>
#include <cuda_fp16.h>
#include <math.h>
#include <stdint.h>

#define D_MODEL 1024
#define N_HEADS 16
#define HEAD_DIM 64
#define BATCH 2
#define SEQ 2048
#define M_TOT (BATCH * SEQ)   /* 4096 */

/* ---- scratch (allocation-free: __device__ globals) ---- */
__device__ __half g_xh[(size_t)M_TOT * D_MODEL];
__device__ __half g_wh[4][(size_t)D_MODEL * D_MODEL];
__device__ __half g_qp[(size_t)M_TOT * D_MODEL];   /* q proj (pre-rope) */
__device__ __half g_kp[(size_t)M_TOT * D_MODEL];   /* k proj (pre-rope) */
__device__ __half g_vp[(size_t)M_TOT * D_MODEL];   /* v proj */
__device__ __half g_qh[(size_t)M_TOT * D_MODEL];   /* rope'd q (scaled by 0.125*log2e) */
__device__ __half g_kh[(size_t)M_TOT * D_MODEL];   /* rope'd k */
__device__ __half g_vt[(size_t)M_TOT * D_MODEL];   /* V^T [bh][d][S] */
__device__ __half g_ao[(size_t)M_TOT * D_MODEL];   /* attn out */

__device__ __forceinline__ uint32_t smem_to_u32(const void* p) {
    uint32_t a;
    asm("{ .reg .u64 t; cvta.to.shared.u64 t, %1; cvt.u32.u64 %0, t; }" : "=r"(a) : "l"(p));
    return a;
}

#define LDSM_X4(r0, r1, r2, r3, addr) \
    asm volatile("ldmatrix.sync.aligned.m8n8.x4.shared.b16 {%0,%1,%2,%3}, [%4];" \
                 : "=r"(r0), "=r"(r1), "=r"(r2), "=r"(r3) : "r"(addr))

#define MMA_FP16(c, a, b) \
    asm volatile("mma.sync.aligned.m16n8k16.row.col.f32.f16.f16.f32 " \
                 "{%0,%1,%2,%3},{%4,%5,%6,%7},{%8,%9},{%0,%1,%2,%3};" \
                 : "+f"((c)[0]), "+f"((c)[1]), "+f"((c)[2]), "+f"((c)[3]) \
                 : "r"((a)[0]), "r"((a)[1]), "r"((a)[2]), "r"((a)[3]), \
                   "r"((b)[0]), "r"((b)[1]))

#define CP_ASYNC16(saddr, gptr) \
    asm volatile("cp.async.cg.shared.global [%0], [%1], 16;" \
                 :: "r"(saddr), "l"(gptr) : "memory")
#define CP_COMMIT() asm volatile("cp.async.commit_group;" ::: "memory")
#define CP_WAIT0()  asm volatile("cp.async.wait_group 0;" ::: "memory")
#define CP_WAIT1()  asm volatile("cp.async.wait_group 1;" ::: "memory")

__device__ __forceinline__ uint32_t pk_h2(float a, float b) {
    __half2 h = __floats2half2_rn(a, b);
    return *(uint32_t*)&h;
}

/* ============================================================
 * Merged fp32 -> fp16 conversion for x + all 4 weights.
 * ============================================================ */
__global__ void __launch_bounds__(256)
convert_all_kernel(const float* __restrict__ x,
                   const float* __restrict__ w0, const float* __restrict__ w1,
                   const float* __restrict__ w2, const float* __restrict__ w3,
                   __half* __restrict__ xh, __half* __restrict__ wh)
{
    const int b = blockIdx.x;
    const float* src;
    __half* dst;
    int lb;
    if (b < 4096) { src = x; dst = xh; lb = b; }
    else {
        const int r = b - 4096;
        const int w = r >> 10;
        src = (w == 0) ? w0 : (w == 1) ? w1 : (w == 2) ? w2 : w3;
        dst = wh + (size_t)w * D_MODEL * D_MODEL;
        lb = r & 1023;
    }
    const size_t i = ((size_t)lb * 256 + threadIdx.x) * 4;
    float4 v = *(const float4*)(src + i);
    *(uint2*)(dst + i) = make_uint2(pk_h2(v.x, v.y), pk_h2(v.z, v.w));
}

/* ============================================================
 * fp16 single-pass GEMM core, BK=64 (unchanged, proven).
 * ============================================================ */
#define SPITCH 144
#define TBYTES (128 * SPITCH)
#define GSTG (2 * TBYTES)
#define GEMM_SMEM (2 * GSTG)   /* 73728 */

template <typename OutT>
__device__ __forceinline__ void
gemm_core(const __half* __restrict__ A, const __half* __restrict__ B,
          OutT* __restrict__ C, int m0, int n0, int K, int N, char* smem)
{
    const uint32_t su = smem_to_u32(smem);
    const int tid    = threadIdx.x;
    const int lane   = tid & 31;
    const int wid    = tid >> 5;
    const int warp_m = wid >> 2;
    const int warp_n = wid & 3;

    const int nchunks = K / 64;

    auto issue_stage = [&](int s, int i) {
        const uint32_t sb = su + s * GSTG;
        #pragma unroll
        for (int t = 0; t < 4; t++) {
            const int idx = tid + t * 256;
            const int row = idx >> 3, c = idx & 7;
            const uint32_t so = (uint32_t)row * SPITCH + c * 16;
            const size_t ga = (size_t)(m0 + row) * K + i * 64 + c * 8;
            const size_t gb = (size_t)(n0 + row) * K + i * 64 + c * 8;
            CP_ASYNC16(sb + so, A + ga);
            CP_ASYNC16(sb + TBYTES + so, B + gb);
        }
        CP_COMMIT();
    };

    issue_stage(0, 0);

    const uint32_t a_ld = su + (uint32_t)(warp_m * 64 + (lane & 15)) * SPITCH + (lane >> 4) * 16;
    const uint32_t b_ld = su + TBYTES + (uint32_t)(warp_n * 32 + (lane & 15)) * SPITCH + (lane >> 4) * 16;

    float acc[4][4][4] = {};

    for (int i = 0; i < nchunks; i++) {
        const int s = i & 1;
        if (i + 1 < nchunks) { issue_stage(s ^ 1, i + 1); CP_WAIT1(); }
        else                 { CP_WAIT0(); }
        __syncthreads();

        const uint32_t stb = s * GSTG;
        #pragma unroll
        for (int ks = 0; ks < 4; ks++) {
            uint32_t af[4][4];
            #pragma unroll
            for (int mt = 0; mt < 4; mt++)
                LDSM_X4(af[mt][0], af[mt][1], af[mt][2], af[mt][3],
                        a_ld + stb + mt * 16 * SPITCH + ks * 32);
            uint32_t bf[4][2];
            #pragma unroll
            for (int nb = 0; nb < 2; nb++) {
                uint32_t r0, r1, r2, r3;
                LDSM_X4(r0, r1, r2, r3, b_ld + stb + nb * 16 * SPITCH + ks * 32);
                bf[nb * 2][0]     = r0; bf[nb * 2][1]     = r2;
                bf[nb * 2 + 1][0] = r1; bf[nb * 2 + 1][1] = r3;
            }
            #pragma unroll
            for (int mt = 0; mt < 4; mt++)
                #pragma unroll
                for (int nt = 0; nt < 4; nt++)
                    MMA_FP16(acc[mt][nt], af[mt], bf[nt]);
        }
        __syncthreads();
    }

    #pragma unroll
    for (int mt = 0; mt < 4; mt++) {
        const int m = m0 + warp_m * 64 + mt * 16 + (lane >> 2);
        #pragma unroll
        for (int nt = 0; nt < 4; nt++) {
            const int n = n0 + warp_n * 32 + nt * 8 + (lane & 3) * 2;
            if constexpr (sizeof(OutT) == 2) {
                *(uint32_t*)((__half*)C + (size_t)m * N + n) =
                    pk_h2(acc[mt][nt][0], acc[mt][nt][1]);
                *(uint32_t*)((__half*)C + (size_t)(m + 8) * N + n) =
                    pk_h2(acc[mt][nt][2], acc[mt][nt][3]);
            } else {
                *(float2*)((float*)C + (size_t)m * N + n) =
                    make_float2(acc[mt][nt][0], acc[mt][nt][1]);
                *(float2*)((float*)C + (size_t)(m + 8) * N + n) =
                    make_float2(acc[mt][nt][2], acc[mt][nt][3]);
            }
        }
    }
}

__global__ void __launch_bounds__(256, 2)
gemm_qkv_kernel(const __half* __restrict__ xh, const __half* __restrict__ wh,
                __half* __restrict__ q, __half* __restrict__ k, __half* __restrict__ v)
{
    extern __shared__ __align__(16) char smem[];
    const int w  = blockIdx.x >> 3;
    const int n0 = (blockIdx.x & 7) * 128;
    const int m0 = blockIdx.y * 128;
    const __half* B = wh + (size_t)w * D_MODEL * D_MODEL;
    __half* C = (w == 0) ? q : (w == 1) ? k : v;
    gemm_core<__half>(xh, B, C, m0, n0, D_MODEL, D_MODEL, smem);
}

__global__ void __launch_bounds__(256, 2)
gemm_fp16_kernel(const __half* __restrict__ A, const __half* __restrict__ B,
                 float* __restrict__ C)
{
    extern __shared__ __align__(16) char smem[];
    gemm_core<float>(A, B, C, blockIdx.y * 128, blockIdx.x * 128, D_MODEL, D_MODEL, smem);
}

/* ============================================================
 * Fused RoPE (blocks 0..511) + V-transpose (blocks 512..1535).
 * Q scaled by 0.125*log2(e) (exp2-domain softmax downstream).
 * ============================================================ */
#define QSCALE (0.125f * 1.4426950408889634f)

__global__ void __launch_bounds__(256)
rope_vtrans_kernel(const __half* __restrict__ qp, const __half* __restrict__ kp,
                   const __half* __restrict__ vp,
                   __half* __restrict__ qh, __half* __restrict__ kh,
                   __half* __restrict__ vt)
{
    __shared__ float t[64][65];
    const int tid = threadIdx.x;

    if (blockIdx.x < 512) {
        __shared__ float invf[32];
        if (tid < 32) invf[tid] = (float)pow(10000.0, -(double)tid / 32.0);
        __syncthreads();

        const int bs   = blockIdx.x * 8 + (tid >> 5);
        const int lane = tid & 31;
        const int pos  = bs & (SEQ - 1);

        float s1, c1, s2, c2;
        sincosf((float)pos * invf[(2 * lane) & 31],     &s1, &c1);
        sincosf((float)pos * invf[(2 * lane + 1) & 31], &s2, &c2);

        const size_t base = (size_t)bs * D_MODEL;
        #pragma unroll
        for (int h = 0; h < N_HEADS; h++) {
            const size_t ro = base + h * 64;
            {
                __half2 xv = *(const __half2*)(qp + ro + 2 * lane);
                float x0 = __low2float(xv), x1 = __high2float(xv);
                qh[ro + lane]      = __float2half_rn((x0 * c1 - x1 * s1) * QSCALE);
                qh[ro + 32 + lane] = __float2half_rn((x0 * s2 + x1 * c2) * QSCALE);
            }
            {
                __half2 xv = *(const __half2*)(kp + ro + 2 * lane);
                float x0 = __low2float(xv), x1 = __high2float(xv);
                kh[ro + lane]      = __float2half_rn(x0 * c1 - x1 * s1);
                kh[ro + 32 + lane] = __float2half_rn(x0 * s2 + x1 * c2);
            }
        }
    } else {
        const int r    = blockIdx.x - 512;
        const int sblk = r & 31;
        const int bh   = r >> 5;

        {
            const int row = tid >> 2;
            const int c0  = (tid & 3) * 16;
            const size_t gaddr = ((size_t)(bh >> 4) * SEQ + sblk * 64 + row) * D_MODEL
                               + (bh & 15) * 64 + c0;
            #pragma unroll
            for (int f = 0; f < 2; f++) {
                uint4 pk = *(const uint4*)(vp + gaddr + f * 8);
                const __half* hp = (const __half*)&pk;
                #pragma unroll
                for (int e = 0; e < 8; e++)
                    t[row][c0 + f * 8 + e] = __half2float(hp[e]);
            }
        }
        __syncthreads();

        const int d  = tid >> 2;
        const int k0 = (tid & 3) * 16;
        uint32_t out[8];
        #pragma unroll
        for (int p = 0; p < 8; p++)
            out[p] = pk_h2(t[k0 + 2 * p][d], t[k0 + 2 * p + 1][d]);
        const size_t dst = ((size_t)bh * 64 + d) * SEQ + sblk * 64 + k0;
        *(uint4*)(vt + dst)     = *(uint4*)(out);
        *(uint4*)(vt + dst + 8) = *(uint4*)(out + 4);
    }
}

/* ============================================================
 * Flash attention, causal, single-pass fp16 mma, exp2 softmax,
 * 3-stage cp.async pipeline with ONE syncthreads per key-tile.
 * ============================================================ */
#define AQP 144
#define AQT (128 * AQP)        /* 18432 */
#define AKT (64 * AQP)         /* 9216 */
#define ASTG (2 * AKT)         /* K + V = 18432 */
#define ATTN_SMEM (AQT + 3 * ASTG)   /* 73728 */
#define NQB (SEQ / 128)

__global__ void __launch_bounds__(256, 2)
attn_mma_kernel(const __half* __restrict__ qh, const __half* __restrict__ kh,
                const __half* __restrict__ vt, __half* __restrict__ o)
{
    extern __shared__ __align__(16) char sm[];
    const uint32_t su = smem_to_u32(sm);

    const int bh   = blockIdx.y;
    const int tid  = threadIdx.x;
    const int lane = tid & 31;
    const int wid  = tid >> 5;

    const int b = bh >> 4, h = bh & 15;
    const size_t qkrow0 = ((size_t)b * SEQ) * D_MODEL + (size_t)h * 64;
    const size_t vtrow0 = ((size_t)bh * 64) * SEQ;

    const uint32_t a_ld = su + (uint32_t)(wid * 16 + (lane & 15)) * AQP + (lane >> 4) * 16;
    const uint32_t t_ld = su + AQT + (uint32_t)(lane & 15) * AQP + (lane >> 4) * 16;

    auto issue_stage = [&](int s, int kb) {
        const uint32_t sb = su + AQT + s * ASTG;
        #pragma unroll
        for (int i = 0; i < 2; i++) {
            const int idx = tid + i * 256;
            const int row = idx >> 3, c = idx & 7;
            const uint32_t so = (uint32_t)row * AQP + c * 16;
            const size_t gk = qkrow0 + (size_t)(kb * 64 + row) * D_MODEL + c * 8;
            const size_t gv = vtrow0 + (size_t)row * SEQ + kb * 64 + c * 8;
            CP_ASYNC16(sb + so, kh + gk);
            CP_ASYNC16(sb + AKT + so, vt + gv);
        }
        CP_COMMIT();
    };

    #pragma unroll 1
    for (int qi = 0; qi < 2; qi++) {
        const int qb = (qi == 0) ? blockIdx.x : (NQB - 1 - blockIdx.x);

        {
            #pragma unroll
            for (int i = 0; i < 4; i++) {
                const int idx = tid + i * 256;
                const int row = idx >> 3, c = idx & 7;
                const size_t g = qkrow0 + (size_t)(qb * 128 + row) * D_MODEL + c * 8;
                *(uint4*)(sm + (size_t)row * AQP + c * 16) = *(const uint4*)(qh + g);
            }
        }

        const int nkb = 2 * qb + 2;
        issue_stage(0, 0);
        if (nkb > 1) issue_stage(1, 1);

        float acc[8][4] = {};
        float mo1 = -1e30f, mo2 = -1e30f, l1 = 0.0f, l2 = 0.0f;
        const int q1g = qb * 128 + wid * 16 + (lane >> 2);
        const int warp_qmax = qb * 128 + wid * 16 + 15;

        for (int kb = 0; kb < nkb; kb++) {
            if (kb + 1 < nkb) { CP_WAIT1(); }
            else              { CP_WAIT0(); }
            __syncthreads();
            /* stage (kb+2)%3 was consumed at iter kb-1 -> safe to refill */
            if (kb + 2 < nkb) issue_stage((kb + 2) % 3, kb + 2);

            const bool tile_active = (kb * 64 <= warp_qmax);

            if (tile_active) {
                const uint32_t k_ld = t_ld + (uint32_t)(kb % 3) * ASTG;
                const uint32_t v_ld = k_ld + AKT;

                float sc[8][4] = {};
                #pragma unroll
                for (int ks = 0; ks < 4; ks++) {
                    uint32_t af[4];
                    LDSM_X4(af[0], af[1], af[2], af[3], a_ld + ks * 32);
                    #pragma unroll
                    for (int nb = 0; nb < 4; nb++) {
                        if (kb * 64 + nb * 16 > warp_qmax) continue;
                        uint32_t r0, r1, r2, r3;
                        LDSM_X4(r0, r1, r2, r3, k_ld + nb * 16 * AQP + ks * 32);
                        uint32_t be[2] = {r0, r2}, bo[2] = {r1, r3};
                        MMA_FP16(sc[2 * nb],     af, be);
                        MMA_FP16(sc[2 * nb + 1], af, bo);
                    }
                }

                if (kb * 64 + 63 > qb * 128 + wid * 16) {
                    #pragma unroll
                    for (int j = 0; j < 8; j++) {
                        const int c = kb * 64 + j * 8 + (lane & 3) * 2;
                        if (c     > q1g)     sc[j][0] = -1e30f;
                        if (c + 1 > q1g)     sc[j][1] = -1e30f;
                        if (c     > q1g + 8) sc[j][2] = -1e30f;
                        if (c + 1 > q1g + 8) sc[j][3] = -1e30f;
                    }
                }

                /* online softmax in exp2 domain (Q pre-scaled by log2e) */
                float m1 = -1e30f, m2 = -1e30f;
                #pragma unroll
                for (int j = 0; j < 8; j++) {
                    m1 = fmaxf(m1, fmaxf(sc[j][0], sc[j][1]));
                    m2 = fmaxf(m2, fmaxf(sc[j][2], sc[j][3]));
                }
                m1 = fmaxf(m1, __shfl_xor_sync(0xffffffffu, m1, 1));
                m1 = fmaxf(m1, __shfl_xor_sync(0xffffffffu, m1, 2));
                m2 = fmaxf(m2, __shfl_xor_sync(0xffffffffu, m2, 1));
                m2 = fmaxf(m2, __shfl_xor_sync(0xffffffffu, m2, 2));
                const float mn1 = fmaxf(mo1, m1), mn2 = fmaxf(mo2, m2);
                const float sc1 = exp2f(mo1 - mn1), sc2 = exp2f(mo2 - mn2);
                float sum1 = 0.0f, sum2 = 0.0f;
                #pragma unroll
                for (int j = 0; j < 8; j++) {
                    sc[j][0] = exp2f(sc[j][0] - mn1); sum1 += sc[j][0];
                    sc[j][1] = exp2f(sc[j][1] - mn1); sum1 += sc[j][1];
                    sc[j][2] = exp2f(sc[j][2] - mn2); sum2 += sc[j][2];
                    sc[j][3] = exp2f(sc[j][3] - mn2); sum2 += sc[j][3];
                }
                sum1 += __shfl_xor_sync(0xffffffffu, sum1, 1);
                sum1 += __shfl_xor_sync(0xffffffffu, sum1, 2);
                sum2 += __shfl_xor_sync(0xffffffffu, sum2, 1);
                sum2 += __shfl_xor_sync(0xffffffffu, sum2, 2);
                l1 = l1 * sc1 + sum1; l2 = l2 * sc2 + sum2;
                mo1 = mn1; mo2 = mn2;
                #pragma unroll
                for (int j = 0; j < 8; j++) {
                    acc[j][0] *= sc1; acc[j][1] *= sc1;
                    acc[j][2] *= sc2; acc[j][3] *= sc2;
                }

                #pragma unroll
                for (int kt = 0; kt < 4; kt++) {
                    if (kb * 64 + kt * 16 > warp_qmax) continue;
                    uint32_t pa[4];
                    pa[0] = pk_h2(sc[2 * kt][0],     sc[2 * kt][1]);
                    pa[1] = pk_h2(sc[2 * kt][2],     sc[2 * kt][3]);
                    pa[2] = pk_h2(sc[2 * kt + 1][0], sc[2 * kt + 1][1]);
                    pa[3] = pk_h2(sc[2 * kt + 1][2], sc[2 * kt + 1][3]);
                    #pragma unroll
                    for (int nb = 0; nb < 4; nb++) {
                        uint32_t r0, r1, r2, r3;
                        LDSM_X4(r0, r1, r2, r3, v_ld + nb * 16 * AQP + kt * 32);
                        uint32_t be[2] = {r0, r2}, bo[2] = {r1, r3};
                        MMA_FP16(acc[2 * nb],     pa, be);
                        MMA_FP16(acc[2 * nb + 1], pa, bo);
                    }
                }
            }
        }

        __syncthreads();   /* all reads done before epilogue + next qi Q load */
        const float i1 = 1.0f / l1, i2 = 1.0f / l2;
        const size_t r1a = qkrow0 + (size_t)(qb * 128 + wid * 16 + (lane >> 2)) * D_MODEL;
        const size_t r2a = r1a + 8 * D_MODEL;
        #pragma unroll
        for (int j = 0; j < 8; j++) {
            const int c = j * 8 + (lane & 3) * 2;
            *(uint32_t*)(o + r1a + c) = pk_h2(acc[j][0] * i1, acc[j][1] * i1);
            *(uint32_t*)(o + r2a + c) = pk_h2(acc[j][2] * i2, acc[j][3] * i2);
        }
        __syncthreads();
    }
}

/* ============================================================ */
extern "C" void kernel_launch(void* const* d_in, const int* in_sizes, int n_in,
                              void* d_out, int out_size)
{
    const float* x  = (const float*)d_in[0];
    const float* W[4] = { (const float*)d_in[1], (const float*)d_in[2],
                          (const float*)d_in[3], (const float*)d_in[4] };
    float* out = (float*)d_out;

    __half *xh, *wh, *qpp, *kpp, *vpp, *qhp, *khp, *vtp, *aop;
    cudaGetSymbolAddress((void**)&xh, g_xh);
    cudaGetSymbolAddress((void**)&wh, g_wh);
    cudaGetSymbolAddress((void**)&qpp, g_qp);
    cudaGetSymbolAddress((void**)&kpp, g_kp);
    cudaGetSymbolAddress((void**)&vpp, g_vp);
    cudaGetSymbolAddress((void**)&qhp, g_qh);
    cudaGetSymbolAddress((void**)&khp, g_kh);
    cudaGetSymbolAddress((void**)&vtp, g_vt);
    cudaGetSymbolAddress((void**)&aop, g_ao);

    static bool attr_done = false;
    if (!attr_done) {
        cudaFuncSetAttribute(gemm_qkv_kernel,
                             cudaFuncAttributeMaxDynamicSharedMemorySize, GEMM_SMEM);
        cudaFuncSetAttribute(gemm_fp16_kernel,
                             cudaFuncAttributeMaxDynamicSharedMemorySize, GEMM_SMEM);
        cudaFuncSetAttribute(attn_mma_kernel,
                             cudaFuncAttributeMaxDynamicSharedMemorySize, ATTN_SMEM);
        attr_done = true;
    }

    const size_t WSZ = (size_t)D_MODEL * D_MODEL;

    convert_all_kernel<<<8192, 256>>>(x, W[0], W[1], W[2], W[3], xh, wh);

    gemm_qkv_kernel<<<dim3(24, M_TOT / 128), 256, GEMM_SMEM>>>(xh, wh, qpp, kpp, vpp);

    rope_vtrans_kernel<<<1536, 256>>>(qpp, kpp, vpp, qhp, khp, vtp);

    attn_mma_kernel<<<dim3(NQB / 2, BATCH * N_HEADS), 256, ATTN_SMEM>>>(
        qhp, khp, vtp, aop);

    gemm_fp16_kernel<<<dim3(8, M_TOT / 128), 256, GEMM_SMEM>>>(aop, wh + 3 * WSZ, out);
}